// round 13
// baseline (speedup 1.0000x reference)
#include <cuda_runtime.h>
#include <cuda_fp16.h>
#include <cuda_bf16.h>
#include <cstdint>

#define NN 100000
#define NE 1600000

// ---------------- device scratch ----------------
__device__ __half g_eh[(size_t)NE * 64];    // edge features fp16, CSR order
__device__ __half g_zh0[(size_t)NN * 64];
__device__ __half g_zh1[(size_t)NN * 64];
__device__ __half g_u[(size_t)NN * 64];
__device__ float  g_hA[NN * 64];
__device__ float  g_hB[NN * 64];
__device__ int    g_srcn[NE];
__device__ int    g_pos[NE];
__device__ int    g_rank[NE];
__device__ int    g_offs[NN + 1];
__device__ int    g_deg[NN];
__device__ int    g_bsum[128];

// ---------------- CSR build ----------------
__global__ void k_hist(const int* __restrict__ ei) {
    int i = blockIdx.x * blockDim.x + threadIdx.x;
    if (i < NE) g_rank[i] = atomicAdd(&g_deg[ei[NE + i]], 1);
}
__global__ void k_scan1() {
    int t = threadIdx.x;
    int idx = blockIdx.x * 1024 + t;
    int v = (idx < NN) ? g_deg[idx] : 0;
    if (idx < NN) g_deg[idx] = 0;
    int x = v;
    int lane = t & 31, w = t >> 5;
    #pragma unroll
    for (int o = 1; o < 32; o <<= 1) {
        int y = __shfl_up_sync(0xffffffffu, x, o);
        if (lane >= o) x += y;
    }
    __shared__ int ws[32];
    if (lane == 31) ws[w] = x;
    __syncthreads();
    if (w == 0) {
        int y = ws[lane];
        #pragma unroll
        for (int o = 1; o < 32; o <<= 1) {
            int z2 = __shfl_up_sync(0xffffffffu, y, o);
            if (lane >= o) y += z2;
        }
        ws[lane] = y;
    }
    __syncthreads();
    int incl = x + (w > 0 ? ws[w - 1] : 0);
    if (idx < NN) g_offs[idx] = incl - v;
    if (t == 1023) g_bsum[blockIdx.x] = incl;
}
__global__ __launch_bounds__(256) void k_scan23() {
    __shared__ int bs[128];
    __shared__ int ws[4];
    int t = threadIdx.x;
    const int nb = (NN + 1023) >> 10;
    int v = 0, x = 0;
    int lane = t & 31, w = t >> 5;
    if (t < 128) {
        v = (t < nb) ? g_bsum[t] : 0;
        x = v;
        #pragma unroll
        for (int o = 1; o < 32; o <<= 1) {
            int y = __shfl_up_sync(0xffffffffu, x, o);
            if (lane >= o) x += y;
        }
        if (lane == 31) ws[w] = x;
    }
    __syncthreads();
    if (t < 128) {
        int add = 0;
        if (w == 1) add = ws[0];
        else if (w == 2) add = ws[0] + ws[1];
        else if (w == 3) add = ws[0] + ws[1] + ws[2];
        bs[t] = x + add - v;
    }
    __syncthreads();
    int idx = blockIdx.x * 256 + t;
    if (idx < NN) g_offs[idx] += bs[idx >> 10];
    if (idx == 0) g_offs[NN] = NE;
}
__global__ void k_scatter(const int* __restrict__ ei) {
    int i = blockIdx.x * blockDim.x + threadIdx.x;
    if (i < NE) {
        int d = ei[NE + i];
        int p = g_offs[d] + g_rank[i];
        g_srcn[p] = ei[i];
        g_pos[i] = p;
    }
}

// ---------------- GEMM plumbing ----------------
#define LDSM4(R0,R1,R2,R3,ADDR) \
    asm volatile("ldmatrix.sync.aligned.m8n8.x4.shared.b16 {%0,%1,%2,%3}, [%4];" \
        : "=r"(R0),"=r"(R1),"=r"(R2),"=r"(R3) : "r"(ADDR))
#define MMA_F16(C0,C1,C2,C3,A0,A1,A2,A3,B0,B1) \
    asm volatile("mma.sync.aligned.m16n8k16.row.col.f32.f16.f16.f32 " \
        "{%0,%1,%2,%3},{%4,%5,%6,%7},{%8,%9},{%0,%1,%2,%3};" \
        : "+f"(C0),"+f"(C1),"+f"(C2),"+f"(C3) \
        : "r"(A0),"r"(A1),"r"(A2),"r"(A3),"r"(B0),"r"(B1))

__device__ __forceinline__ uint32_t sm_addr(const void* p) {
    return (uint32_t)__cvta_generic_to_shared(p);
}
__device__ __forceinline__ uint32_t hf2u(float a, float b) {
    __half2 v = __floats2half2_rn(a, b);
    return *(uint32_t*)&v;
}
__device__ __forceinline__ float ex2f(float x) {
    float r; asm("ex2.approx.f32 %0, %1;" : "=f"(r) : "f"(x)); return r;
}

// ---------------- node encoder: fp16 A + fp16 W single-pass, fp16 out --------
template<int TILES>
__global__ __launch_bounds__(128) void k_gemm_node(
    const float* __restrict__ A,
    const float* __restrict__ W, const float* __restrict__ bias,
    __half* __restrict__ outH)
{
    __shared__ __align__(16) char smraw[9216];
    __half (*Wh)[72]  = (__half(*)[72])smraw;
    __half (*Ahh)[72] = (__half(*)[72])smraw;

    int t = threadIdx.x;
    int w = t >> 5, lane = t & 31;
    int tr = lane & 7, sel = lane >> 3;

    for (int i = t; i < 4096; i += 128) {
        int k = i >> 6, n = i & 63;
        Wh[n][k] = __float2half_rn(W[i]);
    }
    __syncthreads();

    int c0 = w * 16;
    uint32_t bh[4][4];
    {
        int bn = c0 + tr + ((sel & 2) << 2);
        #pragma unroll
        for (int k = 0; k < 4; k++) {
            int bk = 16 * k + ((sel & 1) << 3);
            LDSM4(bh[k][0], bh[k][1], bh[k][2], bh[k][3], sm_addr(&Wh[bn][bk]));
        }
    }
    __syncthreads();

    float bi[2][2];
    #pragma unroll
    for (int s = 0; s < 2; s++) {
        int cs = c0 + s * 8 + (lane & 3) * 2;
        bi[s][0] = __ldg(&bias[cs]);
        bi[s][1] = __ldg(&bias[cs + 1]);
    }

    int r = t >> 3, q = t & 7;
    int ar = tr + ((sel & 1) << 3);

    long ti0 = (long)blockIdx.x * TILES;
    float4 pfa = __ldcs((const float4*)(A + (ti0 * 16 + r) * 64 + q * 8));
    float4 pfb = __ldcs((const float4*)(A + (ti0 * 16 + r) * 64 + q * 8 + 4));

    for (int it = 0; it < TILES; it++) {
        long ti = ti0 + it;
        {
            uint4 hv;
            hv.x = hf2u(pfa.x, pfa.y); hv.y = hf2u(pfa.z, pfa.w);
            hv.z = hf2u(pfb.x, pfb.y); hv.w = hf2u(pfb.z, pfb.w);
            *(uint4*)&Ahh[r][q * 8] = hv;
        }
        __syncthreads();

        if (it + 1 < TILES) {
            pfa = __ldcs((const float4*)(A + ((ti + 1) * 16 + r) * 64 + q * 8));
            pfb = __ldcs((const float4*)(A + ((ti + 1) * 16 + r) * 64 + q * 8 + 4));
        }

        float acc[2][4];
        #pragma unroll
        for (int s = 0; s < 2; s++) {
            acc[s][0] = bi[s][0]; acc[s][1] = bi[s][1];
            acc[s][2] = bi[s][0]; acc[s][3] = bi[s][1];
        }

        #pragma unroll
        for (int k = 0; k < 4; k++) {
            int ak = 16 * k + ((sel >> 1) << 3);
            uint32_t a0, a1, a2, a3;
            LDSM4(a0, a1, a2, a3, sm_addr(&Ahh[ar][ak]));
            MMA_F16(acc[0][0],acc[0][1],acc[0][2],acc[0][3], a0,a1,a2,a3, bh[k][0],bh[k][1]);
            MMA_F16(acc[1][0],acc[1][1],acc[1][2],acc[1][3], a0,a1,a2,a3, bh[k][2],bh[k][3]);
        }
        __syncthreads();

        long rg0 = ti * 16 + (lane >> 2);
        long rg1 = rg0 + 8;
        #pragma unroll
        for (int s = 0; s < 2; s++) {
            int cs = c0 + s * 8 + (lane & 3) * 2;
            *(__half2*)(outH + rg0 * 64 + cs) = __floats2half2_rn(acc[s][0], acc[s][1]);
            *(__half2*)(outH + rg1 * 64 + cs) = __floats2half2_rn(acc[s][2], acc[s][3]);
        }
    }
}

// ---------------- edge encoder: fp16 A + fp16 W single-pass, direct scatter ---
template<int TILES>
__global__ __launch_bounds__(128) void k_gemm_edge(
    const float* __restrict__ A,
    const float* __restrict__ W, const float* __restrict__ bias,
    __half* __restrict__ outH, const int* __restrict__ pos)
{
    __shared__ __align__(16) char smraw[9216];
    __half (*Wh)[72]  = (__half(*)[72])smraw;
    __half (*Ahh)[72] = (__half(*)[72])smraw;

    int t = threadIdx.x;
    int w = t >> 5, lane = t & 31;
    int tr = lane & 7, sel = lane >> 3;

    for (int i = t; i < 4096; i += 128) {
        int k = i >> 6, n = i & 63;
        Wh[n][k] = __float2half_rn(W[i]);
    }
    __syncthreads();

    int c0 = w * 16;
    uint32_t bh[4][4];
    {
        int bn = c0 + tr + ((sel & 2) << 2);
        #pragma unroll
        for (int k = 0; k < 4; k++) {
            int bk = 16 * k + ((sel & 1) << 3);
            LDSM4(bh[k][0], bh[k][1], bh[k][2], bh[k][3], sm_addr(&Wh[bn][bk]));
        }
    }
    __syncthreads();

    float bi[2][2];
    #pragma unroll
    for (int s = 0; s < 2; s++) {
        int cs = c0 + s * 8 + (lane & 3) * 2;
        bi[s][0] = __ldg(&bias[cs]);
        bi[s][1] = __ldg(&bias[cs + 1]);
    }

    int r = t >> 3, q = t & 7;
    int ar = tr + ((sel & 1) << 3);

    long ti0 = (long)blockIdx.x * TILES;
    float4 pfa = __ldcs((const float4*)(A + (ti0 * 16 + r) * 64 + q * 8));
    float4 pfb = __ldcs((const float4*)(A + (ti0 * 16 + r) * 64 + q * 8 + 4));

    for (int it = 0; it < TILES; it++) {
        long ti = ti0 + it;
        {
            uint4 hv;
            hv.x = hf2u(pfa.x, pfa.y); hv.y = hf2u(pfa.z, pfa.w);
            hv.z = hf2u(pfb.x, pfb.y); hv.w = hf2u(pfb.z, pfb.w);
            *(uint4*)&Ahh[r][q * 8] = hv;
        }
        __syncthreads();

        if (it + 1 < TILES) {
            pfa = __ldcs((const float4*)(A + ((ti + 1) * 16 + r) * 64 + q * 8));
            pfb = __ldcs((const float4*)(A + ((ti + 1) * 16 + r) * 64 + q * 8 + 4));
        }

        float acc[2][4];
        #pragma unroll
        for (int s = 0; s < 2; s++) {
            acc[s][0] = bi[s][0]; acc[s][1] = bi[s][1];
            acc[s][2] = bi[s][0]; acc[s][3] = bi[s][1];
        }

        #pragma unroll
        for (int k = 0; k < 4; k++) {
            int ak = 16 * k + ((sel >> 1) << 3);
            uint32_t a0, a1, a2, a3;
            LDSM4(a0, a1, a2, a3, sm_addr(&Ahh[ar][ak]));
            MMA_F16(acc[0][0],acc[0][1],acc[0][2],acc[0][3], a0,a1,a2,a3, bh[k][0],bh[k][1]);
            MMA_F16(acc[1][0],acc[1][1],acc[1][2],acc[1][3], a0,a1,a2,a3, bh[k][2],bh[k][3]);
        }
        __syncthreads();

        long row0 = ti * 16 + (lane >> 2);
        long p0 = (long)__ldg(&pos[row0]);
        long p1 = (long)__ldg(&pos[row0 + 8]);
        #pragma unroll
        for (int s = 0; s < 2; s++) {
            int cs = c0 + s * 8 + (lane & 3) * 2;
            *(__half2*)(outH + p0 * 64 + cs) = __floats2half2_rn(acc[s][0], acc[s][1]);
            *(__half2*)(outH + p1 * 64 + cs) = __floats2half2_rn(acc[s][2], acc[s][3]);
        }
    }
}

// ---------------- final linear: fp16 A single-pass, W fp16 hi/lo, fp32 out ----
template<int TILES>
__global__ __launch_bounds__(128) void k_gemm_h16(
    const __half* __restrict__ A,
    const float* __restrict__ W, const float* __restrict__ bias,
    float* __restrict__ outF)
{
    __shared__ __align__(16) char smraw[18432];
    __half (*Wh)[72]  = (__half(*)[72])smraw;
    __half (*Wl)[72]  = (__half(*)[72])(smraw + 9216);
    __half (*Ahh)[72] = (__half(*)[72])smraw;

    int t = threadIdx.x;
    int w = t >> 5, lane = t & 31;
    int tr = lane & 7, sel = lane >> 3;

    for (int i = t; i < 4096; i += 128) {
        int k = i >> 6, n = i & 63;
        float wv = W[i];
        __half h = __float2half_rn(wv);
        Wh[n][k] = h;
        Wl[n][k] = __float2half_rn(wv - __half2float(h));
    }
    __syncthreads();

    int c0 = w * 16;
    uint32_t bh[4][4], bl[4][4];
    {
        int bn = c0 + tr + ((sel & 2) << 2);
        #pragma unroll
        for (int k = 0; k < 4; k++) {
            int bk = 16 * k + ((sel & 1) << 3);
            LDSM4(bh[k][0], bh[k][1], bh[k][2], bh[k][3], sm_addr(&Wh[bn][bk]));
            LDSM4(bl[k][0], bl[k][1], bl[k][2], bl[k][3], sm_addr(&Wl[bn][bk]));
        }
    }
    __syncthreads();

    float bi[2][2];
    #pragma unroll
    for (int s = 0; s < 2; s++) {
        int cs = c0 + s * 8 + (lane & 3) * 2;
        bi[s][0] = __ldg(&bias[cs]);
        bi[s][1] = __ldg(&bias[cs + 1]);
    }

    int r = t >> 3, q = t & 7;
    int ar = tr + ((sel & 1) << 3);

    long ti0 = (long)blockIdx.x * TILES;
    uint4 pfu = __ldcs((const uint4*)(A + (ti0 * 16 + r) * 64 + q * 8));

    for (int it = 0; it < TILES; it++) {
        long ti = ti0 + it;
        *(uint4*)&Ahh[r][q * 8] = pfu;
        __syncthreads();

        if (it + 1 < TILES)
            pfu = __ldcs((const uint4*)(A + ((ti + 1) * 16 + r) * 64 + q * 8));

        float acc[2][4];
        #pragma unroll
        for (int s = 0; s < 2; s++) {
            acc[s][0] = bi[s][0]; acc[s][1] = bi[s][1];
            acc[s][2] = bi[s][0]; acc[s][3] = bi[s][1];
        }

        #pragma unroll
        for (int k = 0; k < 4; k++) {
            int ak = 16 * k + ((sel >> 1) << 3);
            uint32_t a0, a1, a2, a3;
            LDSM4(a0, a1, a2, a3, sm_addr(&Ahh[ar][ak]));
            MMA_F16(acc[0][0],acc[0][1],acc[0][2],acc[0][3], a0,a1,a2,a3, bh[k][0],bh[k][1]);
            MMA_F16(acc[0][0],acc[0][1],acc[0][2],acc[0][3], a0,a1,a2,a3, bl[k][0],bl[k][1]);
            MMA_F16(acc[1][0],acc[1][1],acc[1][2],acc[1][3], a0,a1,a2,a3, bh[k][2],bh[k][3]);
            MMA_F16(acc[1][0],acc[1][1],acc[1][2],acc[1][3], a0,a1,a2,a3, bl[k][2],bl[k][3]);
        }
        __syncthreads();

        long rg0 = ti * 16 + (lane >> 2);
        long rg1 = rg0 + 8;
        #pragma unroll
        for (int s = 0; s < 2; s++) {
            int cs = c0 + s * 8 + (lane & 3) * 2;
            *(float2*)(outF + rg0 * 64 + cs) = make_float2(acc[s][0], acc[s][1]);
            *(float2*)(outF + rg1 * 64 + cs) = make_float2(acc[s][2], acc[s][3]);
        }
    }
}

// ---------------- conv GEMM (u fp16 exact, W fp16 hi/lo) + LN epilogue --------
template<bool RES, bool FINAL, int TILES>
__global__ __launch_bounds__(128) void k_gemm_conv(
    const __half* __restrict__ U,
    const float* __restrict__ W, const float* __restrict__ bias,
    const float* __restrict__ hres,
    const float* __restrict__ gamma, const float* __restrict__ beta,
    float* __restrict__ houtF, __half* __restrict__ zoutH)
{
    __shared__ __align__(16) char smraw[18432];
    __half (*Wh)[72]  = (__half(*)[72])smraw;
    __half (*Wl)[72]  = (__half(*)[72])(smraw + 9216);
    __half (*Ahh)[72] = (__half(*)[72])smraw;
    float  (*OSf)[72] = (float(*)[72]) (smraw + 2304);

    int t = threadIdx.x;
    int w = t >> 5, lane = t & 31;
    int tr = lane & 7, sel = lane >> 3;

    for (int i = t; i < 4096; i += 128) {
        int k = i >> 6, n = i & 63;
        float wv = W[i];
        __half h = __float2half_rn(wv);
        Wh[n][k] = h;
        Wl[n][k] = __float2half_rn(wv - __half2float(h));
    }
    __syncthreads();

    int c0 = w * 16;
    uint32_t bh[4][4], bl[4][4];
    {
        int bn = c0 + tr + ((sel & 2) << 2);
        #pragma unroll
        for (int k = 0; k < 4; k++) {
            int bk = 16 * k + ((sel & 1) << 3);
            LDSM4(bh[k][0], bh[k][1], bh[k][2], bh[k][3], sm_addr(&Wh[bn][bk]));
            LDSM4(bl[k][0], bl[k][1], bl[k][2], bl[k][3], sm_addr(&Wl[bn][bk]));
        }
    }
    __syncthreads();

    float bi[2][2];
    #pragma unroll
    for (int s = 0; s < 2; s++) {
        int cs = c0 + s * 8 + (lane & 3) * 2;
        bi[s][0] = __ldg(&bias[cs]);
        bi[s][1] = __ldg(&bias[cs + 1]);
    }

    int r = t >> 3, q = t & 7;
    int ar = tr + ((sel & 1) << 3);

    float4 ga0 = __ldg((const float4*)(gamma + q * 8));
    float4 ga1 = __ldg((const float4*)(gamma + q * 8 + 4));
    float4 be0 = __ldg((const float4*)(beta  + q * 8));
    float4 be1 = __ldg((const float4*)(beta  + q * 8 + 4));

    long ti0 = (long)blockIdx.x * TILES;
    uint4 pfu = __ldcs((const uint4*)(U + (ti0 * 16 + r) * 64 + q * 8));

    for (int it = 0; it < TILES; it++) {
        long ti = ti0 + it;
        *(uint4*)&Ahh[r][q * 8] = pfu;
        __syncthreads();

        if (it + 1 < TILES)
            pfu = __ldcs((const uint4*)(U + ((ti + 1) * 16 + r) * 64 + q * 8));

        float acc[2][4];
        #pragma unroll
        for (int s = 0; s < 2; s++) {
            acc[s][0] = bi[s][0]; acc[s][1] = bi[s][1];
            acc[s][2] = bi[s][0]; acc[s][3] = bi[s][1];
        }

        #pragma unroll
        for (int k = 0; k < 4; k++) {
            int ak = 16 * k + ((sel >> 1) << 3);
            uint32_t a0, a1, a2, a3;
            LDSM4(a0, a1, a2, a3, sm_addr(&Ahh[ar][ak]));
            MMA_F16(acc[0][0],acc[0][1],acc[0][2],acc[0][3], a0,a1,a2,a3, bh[k][0],bh[k][1]);
            MMA_F16(acc[0][0],acc[0][1],acc[0][2],acc[0][3], a0,a1,a2,a3, bl[k][0],bl[k][1]);
            MMA_F16(acc[1][0],acc[1][1],acc[1][2],acc[1][3], a0,a1,a2,a3, bh[k][2],bh[k][3]);
            MMA_F16(acc[1][0],acc[1][1],acc[1][2],acc[1][3], a0,a1,a2,a3, bl[k][2],bl[k][3]);
        }
        __syncthreads();

        {
            int r0 = lane >> 2, r1 = r0 + 8;
            #pragma unroll
            for (int s = 0; s < 2; s++) {
                int cs = c0 + s * 8 + (lane & 3) * 2;
                *(float2*)&OSf[r0][cs] = make_float2(acc[s][0], acc[s][1]);
                *(float2*)&OSf[r1][cs] = make_float2(acc[s][2], acc[s][3]);
            }
        }
        __syncthreads();

        {
            long row = ti * 16 + r;
            float4 va = *(float4*)&OSf[r][q * 8];
            float4 vb = *(float4*)&OSf[r][q * 8 + 4];
            if (RES) {
                float4 ha = __ldcs((const float4*)(hres + row * 64 + q * 8));
                float4 hb = __ldcs((const float4*)(hres + row * 64 + q * 8 + 4));
                va.x += ha.x; va.y += ha.y; va.z += ha.z; va.w += ha.w;
                vb.x += hb.x; vb.y += hb.y; vb.z += hb.z; vb.w += hb.w;
            }
            float s = va.x + va.y + va.z + va.w + vb.x + vb.y + vb.z + vb.w;
            float ss = va.x*va.x + va.y*va.y + va.z*va.z + va.w*va.w
                     + vb.x*vb.x + vb.y*vb.y + vb.z*vb.z + vb.w*vb.w;
            #pragma unroll
            for (int m = 1; m < 8; m <<= 1) {
                s  += __shfl_xor_sync(0xffffffffu, s,  m);
                ss += __shfl_xor_sync(0xffffffffu, ss, m);
            }
            float mu = s * (1.0f / 64.0f);
            float var = fmaxf(ss * (1.0f / 64.0f) - mu * mu, 0.0f);
            float rs = rsqrtf(var + 1e-5f);
            float z0 = fmaxf(fmaf((va.x - mu) * rs, ga0.x, be0.x), 0.f);
            float z1 = fmaxf(fmaf((va.y - mu) * rs, ga0.y, be0.y), 0.f);
            float z2 = fmaxf(fmaf((va.z - mu) * rs, ga0.z, be0.z), 0.f);
            float z3 = fmaxf(fmaf((va.w - mu) * rs, ga0.w, be0.w), 0.f);
            float z4 = fmaxf(fmaf((vb.x - mu) * rs, ga1.x, be1.x), 0.f);
            float z5 = fmaxf(fmaf((vb.y - mu) * rs, ga1.y, be1.y), 0.f);
            float z6 = fmaxf(fmaf((vb.z - mu) * rs, ga1.z, be1.z), 0.f);
            float z7 = fmaxf(fmaf((vb.w - mu) * rs, ga1.w, be1.w), 0.f);
            if (!FINAL) {
                *(float4*)(houtF + row * 64 + q * 8)     = va;
                *(float4*)(houtF + row * 64 + q * 8 + 4) = vb;
            }
            uint4 zv;
            zv.x = hf2u(z0, z1); zv.y = hf2u(z2, z3);
            zv.z = hf2u(z4, z5); zv.w = hf2u(z6, z7);
            *(uint4*)(zoutH + row * 64 + q * 8) = zv;
        }
    }
}

// ---------------- aggregation: single persistent wave -----------------------
#define AGG_GRID 888
#define AGG_ROUNDS 15
__global__ __launch_bounds__(256) void k_agg_lite(
    const __half2* __restrict__ z2, const float* __restrict__ tptr,
    __half2* __restrict__ uout)
{
    int t = threadIdx.x;
    int w = t >> 5, l = t & 31;
    float tv = __ldg(tptr);
    float kf = tv * 1.44269504f;
    const __half2 zero2 = __float2half2_rn(0.f);
    const __half2 eps2  = __float2half2_rn(1e-7f);
    const __half2* e2 = (const __half2*)g_eh;

    #pragma unroll 1
    for (int round = 0; round < AGG_ROUNDS; round++) {
        int node = round * (AGG_GRID * 8) + blockIdx.x * 8 + w;
        if (node >= NN) continue;

        int beg = g_offs[node], end = g_offs[node + 1];
        float d0 = 0.f, d1 = 0.f, s0 = 0.f, s1 = 0.f;
        int p = beg;
        for (; p + 4 <= end; p += 4) {
            __half2 ea = __ldcs(&e2[(size_t)p * 32 + l]);
            __half2 eb = __ldcs(&e2[(size_t)(p + 1) * 32 + l]);
            __half2 ec = __ldcs(&e2[(size_t)(p + 2) * 32 + l]);
            __half2 ed = __ldcs(&e2[(size_t)(p + 3) * 32 + l]);
            int i0 = __ldg(&g_srcn[p]);
            int i1 = __ldg(&g_srcn[p + 1]);
            int i2 = __ldg(&g_srcn[p + 2]);
            int i3 = __ldg(&g_srcn[p + 3]);
            __half2 za = __ldg(&z2[(size_t)i0 * 32 + l]);
            __half2 zb = __ldg(&z2[(size_t)i1 * 32 + l]);
            __half2 zc = __ldg(&z2[(size_t)i2 * 32 + l]);
            __half2 zd = __ldg(&z2[(size_t)i3 * 32 + l]);
            __half2 ma = __hadd2(__hmax2(__hadd2(ea, za), zero2), eps2);
            __half2 mb = __hadd2(__hmax2(__hadd2(eb, zb), zero2), eps2);
            __half2 mc = __hadd2(__hmax2(__hadd2(ec, zc), zero2), eps2);
            __half2 md = __hadd2(__hmax2(__hadd2(ed, zd), zero2), eps2);
            float m0, m1, x0, x1;
            m0 = __low2float(ma); m1 = __high2float(ma);
            x0 = ex2f(m0 * kf); x1 = ex2f(m1 * kf);
            d0 += x0; s0 = fmaf(x0, m0, s0);
            d1 += x1; s1 = fmaf(x1, m1, s1);
            m0 = __low2float(mb); m1 = __high2float(mb);
            x0 = ex2f(m0 * kf); x1 = ex2f(m1 * kf);
            d0 += x0; s0 = fmaf(x0, m0, s0);
            d1 += x1; s1 = fmaf(x1, m1, s1);
            m0 = __low2float(mc); m1 = __high2float(mc);
            x0 = ex2f(m0 * kf); x1 = ex2f(m1 * kf);
            d0 += x0; s0 = fmaf(x0, m0, s0);
            d1 += x1; s1 = fmaf(x1, m1, s1);
            m0 = __low2float(md); m1 = __high2float(md);
            x0 = ex2f(m0 * kf); x1 = ex2f(m1 * kf);
            d0 += x0; s0 = fmaf(x0, m0, s0);
            d1 += x1; s1 = fmaf(x1, m1, s1);
        }
        for (; p < end; p++) {
            __half2 ef = __ldcs(&e2[(size_t)p * 32 + l]);
            int si = __ldg(&g_srcn[p]);
            __half2 zv = __ldg(&z2[(size_t)si * 32 + l]);
            __half2 ma = __hadd2(__hmax2(__hadd2(ef, zv), zero2), eps2);
            float m0 = __low2float(ma), m1 = __high2float(ma);
            float x0 = ex2f(m0 * kf), x1 = ex2f(m1 * kf);
            d0 += x0; s0 = fmaf(x0, m0, s0);
            d1 += x1; s1 = fmaf(x1, m1, s1);
        }

        float2 zn = __half22float2(z2[(size_t)node * 32 + l]);
        float u0 = __fdividef(s0, d0 + 1e-16f) + zn.x;
        float u1 = __fdividef(s1, d1 + 1e-16f) + zn.y;
        uout[(size_t)node * 32 + l] = __floats2half2_rn(u0, u1);
    }
}

// ---------------- launch ----------------
extern "C" void kernel_launch(void* const* d_in, const int* in_sizes, int n_in,
                              void* d_out, int out_size)
{
    const float* x         = (const float*)d_in[0];
    const float* edge_attr = (const float*)d_in[1];
    const int*   ei        = (const int*)d_in[2];
    const float* W_ne      = (const float*)d_in[3];
    const float* b_ne      = (const float*)d_in[4];
    const float* W_ee      = (const float*)d_in[5];
    const float* b_ee      = (const float*)d_in[6];
    const float* W_conv    = (const float*)d_in[7];
    const float* b_conv    = (const float*)d_in[8];
    const float* tarr      = (const float*)d_in[9];
    const float* gamma     = (const float*)d_in[10];
    const float* beta      = (const float*)d_in[11];
    const float* W_lin     = (const float*)d_in[12];
    const float* b_lin     = (const float*)d_in[13];
    float* out = (float*)d_out;

    float *p_hA, *p_hB;
    __half *p_eh, *p_zh0, *p_zh1, *p_u;
    int *p_pos;
    cudaGetSymbolAddress((void**)&p_eh,  g_eh);
    cudaGetSymbolAddress((void**)&p_zh0, g_zh0);
    cudaGetSymbolAddress((void**)&p_zh1, g_zh1);
    cudaGetSymbolAddress((void**)&p_u,   g_u);
    cudaGetSymbolAddress((void**)&p_hA,  g_hA);
    cudaGetSymbolAddress((void**)&p_hB,  g_hB);
    cudaGetSymbolAddress((void**)&p_pos, g_pos);

    const int NB_E  = (NE + 255) / 256;
    const int NB_S  = (NN + 1023) / 1024;
    const int NB_SC = (NN + 255) / 256;

    // CSR
    k_hist  <<<NB_E, 256>>>(ei);
    k_scan1 <<<NB_S, 1024>>>();
    k_scan23<<<NB_SC, 256>>>();
    k_scatter<<<NB_E, 256>>>(ei);
    // encoders
    k_gemm_edge<16><<<6250, 128>>>(edge_attr, W_ee, b_ee, p_eh, p_pos);
    k_gemm_node<10><<<625, 128>>>(x, W_ne, b_ne, p_zh0);

    // layer 0
    k_agg_lite<<<AGG_GRID, 256>>>((const __half2*)p_zh0, tarr, (__half2*)p_u);
    k_gemm_conv<false, false, 10><<<625, 128>>>(p_u, W_conv, b_conv, nullptr,
        gamma + 64, beta + 64, p_hB, p_zh1);
    // layer 1
    k_agg_lite<<<AGG_GRID, 256>>>((const __half2*)p_zh1, tarr + 1, (__half2*)p_u);
    k_gemm_conv<true, false, 10><<<625, 128>>>(p_u, W_conv + 4096, b_conv + 64, p_hB,
        gamma + 128, beta + 128, p_hA, p_zh0);
    // layer 2
    k_agg_lite<<<AGG_GRID, 256>>>((const __half2*)p_zh0, tarr + 2, (__half2*)p_u);
    k_gemm_conv<true, false, 10><<<625, 128>>>(p_u, W_conv + 8192, b_conv + 128, p_hA,
        gamma + 192, beta + 192, p_hB, p_zh1);
    // layer 3 (FINAL: z fp16 only, LN with gamma0/beta0)
    k_agg_lite<<<AGG_GRID, 256>>>((const __half2*)p_zh1, tarr + 3, (__half2*)p_u);
    k_gemm_conv<true, true, 10><<<625, 128>>>(p_u, W_conv + 12288, b_conv + 192, p_hB,
        gamma, beta, nullptr, p_zh0);

    // final linear (fp16 z input)
    k_gemm_h16<10><<<625, 128>>>(p_zh0, W_lin, b_lin, out);
}

// round 14
// speedup vs baseline: 1.0158x; 1.0158x over previous
#include <cuda_runtime.h>
#include <cuda_fp16.h>
#include <cuda_bf16.h>
#include <cstdint>

#define NN 100000
#define NE 1600000

// ---------------- device scratch ----------------
__device__ __half g_eh[(size_t)NE * 64];    // edge features fp16, CSR order
__device__ __half g_zh0[(size_t)NN * 64];
__device__ __half g_zh1[(size_t)NN * 64];
__device__ __half g_u[(size_t)NN * 64];
__device__ float  g_hA[NN * 64];
__device__ float  g_hB[NN * 64];
__device__ int    g_srcn[NE];
__device__ int    g_pos[NE];
__device__ int    g_rank[NE];
__device__ int    g_offs[NN + 1];
__device__ int    g_deg[NN];
__device__ int    g_bsum[128];

// ---------------- CSR build ----------------
__global__ void k_hist(const int* __restrict__ ei) {
    int i = blockIdx.x * blockDim.x + threadIdx.x;
    if (i < NE) g_rank[i] = atomicAdd(&g_deg[ei[NE + i]], 1);
}
__global__ void k_scan1() {
    int t = threadIdx.x;
    int idx = blockIdx.x * 1024 + t;
    int v = (idx < NN) ? g_deg[idx] : 0;
    if (idx < NN) g_deg[idx] = 0;
    int x = v;
    int lane = t & 31, w = t >> 5;
    #pragma unroll
    for (int o = 1; o < 32; o <<= 1) {
        int y = __shfl_up_sync(0xffffffffu, x, o);
        if (lane >= o) x += y;
    }
    __shared__ int ws[32];
    if (lane == 31) ws[w] = x;
    __syncthreads();
    if (w == 0) {
        int y = ws[lane];
        #pragma unroll
        for (int o = 1; o < 32; o <<= 1) {
            int z2 = __shfl_up_sync(0xffffffffu, y, o);
            if (lane >= o) y += z2;
        }
        ws[lane] = y;
    }
    __syncthreads();
    int incl = x + (w > 0 ? ws[w - 1] : 0);
    if (idx < NN) g_offs[idx] = incl - v;
    if (t == 1023) g_bsum[blockIdx.x] = incl;
}
__global__ __launch_bounds__(256) void k_scan23() {
    __shared__ int bs[128];
    __shared__ int ws[4];
    int t = threadIdx.x;
    const int nb = (NN + 1023) >> 10;
    int v = 0, x = 0;
    int lane = t & 31, w = t >> 5;
    if (t < 128) {
        v = (t < nb) ? g_bsum[t] : 0;
        x = v;
        #pragma unroll
        for (int o = 1; o < 32; o <<= 1) {
            int y = __shfl_up_sync(0xffffffffu, x, o);
            if (lane >= o) x += y;
        }
        if (lane == 31) ws[w] = x;
    }
    __syncthreads();
    if (t < 128) {
        int add = 0;
        if (w == 1) add = ws[0];
        else if (w == 2) add = ws[0] + ws[1];
        else if (w == 3) add = ws[0] + ws[1] + ws[2];
        bs[t] = x + add - v;
    }
    __syncthreads();
    int idx = blockIdx.x * 256 + t;
    if (idx < NN) g_offs[idx] += bs[idx >> 10];
    if (idx == 0) g_offs[NN] = NE;
}
__global__ void k_scatter(const int* __restrict__ ei) {
    int i = blockIdx.x * blockDim.x + threadIdx.x;
    if (i < NE) {
        int d = ei[NE + i];
        int p = g_offs[d] + g_rank[i];
        g_srcn[p] = ei[i];
        g_pos[i] = p;
    }
}

// ---------------- GEMM plumbing ----------------
#define LDSM4(R0,R1,R2,R3,ADDR) \
    asm volatile("ldmatrix.sync.aligned.m8n8.x4.shared.b16 {%0,%1,%2,%3}, [%4];" \
        : "=r"(R0),"=r"(R1),"=r"(R2),"=r"(R3) : "r"(ADDR))
#define MMA_F16(C0,C1,C2,C3,A0,A1,A2,A3,B0,B1) \
    asm volatile("mma.sync.aligned.m16n8k16.row.col.f32.f16.f16.f32 " \
        "{%0,%1,%2,%3},{%4,%5,%6,%7},{%8,%9},{%0,%1,%2,%3};" \
        : "+f"(C0),"+f"(C1),"+f"(C2),"+f"(C3) \
        : "r"(A0),"r"(A1),"r"(A2),"r"(A3),"r"(B0),"r"(B1))

__device__ __forceinline__ uint32_t sm_addr(const void* p) {
    return (uint32_t)__cvta_generic_to_shared(p);
}
__device__ __forceinline__ uint32_t hf2u(float a, float b) {
    __half2 v = __floats2half2_rn(a, b);
    return *(uint32_t*)&v;
}
__device__ __forceinline__ float ex2f(float x) {
    float r; asm("ex2.approx.f32 %0, %1;" : "=f"(r) : "f"(x)); return r;
}

// ---------------- node encoder: fp16 A + fp16 W single-pass, fp16 out --------
template<int TILES>
__global__ __launch_bounds__(128) void k_gemm_node(
    const float* __restrict__ A,
    const float* __restrict__ W, const float* __restrict__ bias,
    __half* __restrict__ outH)
{
    __shared__ __align__(16) char smraw[9216];
    __half (*Wh)[72]  = (__half(*)[72])smraw;
    __half (*Ahh)[72] = (__half(*)[72])smraw;

    int t = threadIdx.x;
    int w = t >> 5, lane = t & 31;
    int tr = lane & 7, sel = lane >> 3;

    for (int i = t; i < 4096; i += 128) {
        int k = i >> 6, n = i & 63;
        Wh[n][k] = __float2half_rn(W[i]);
    }
    __syncthreads();

    int c0 = w * 16;
    uint32_t bh[4][4];
    {
        int bn = c0 + tr + ((sel & 2) << 2);
        #pragma unroll
        for (int k = 0; k < 4; k++) {
            int bk = 16 * k + ((sel & 1) << 3);
            LDSM4(bh[k][0], bh[k][1], bh[k][2], bh[k][3], sm_addr(&Wh[bn][bk]));
        }
    }
    __syncthreads();

    float bi[2][2];
    #pragma unroll
    for (int s = 0; s < 2; s++) {
        int cs = c0 + s * 8 + (lane & 3) * 2;
        bi[s][0] = __ldg(&bias[cs]);
        bi[s][1] = __ldg(&bias[cs + 1]);
    }

    int r = t >> 3, q = t & 7;
    int ar = tr + ((sel & 1) << 3);

    long ti0 = (long)blockIdx.x * TILES;
    float4 pfa = __ldcs((const float4*)(A + (ti0 * 16 + r) * 64 + q * 8));
    float4 pfb = __ldcs((const float4*)(A + (ti0 * 16 + r) * 64 + q * 8 + 4));

    for (int it = 0; it < TILES; it++) {
        long ti = ti0 + it;
        {
            uint4 hv;
            hv.x = hf2u(pfa.x, pfa.y); hv.y = hf2u(pfa.z, pfa.w);
            hv.z = hf2u(pfb.x, pfb.y); hv.w = hf2u(pfb.z, pfb.w);
            *(uint4*)&Ahh[r][q * 8] = hv;
        }
        __syncthreads();

        if (it + 1 < TILES) {
            pfa = __ldcs((const float4*)(A + ((ti + 1) * 16 + r) * 64 + q * 8));
            pfb = __ldcs((const float4*)(A + ((ti + 1) * 16 + r) * 64 + q * 8 + 4));
        }

        float acc[2][4];
        #pragma unroll
        for (int s = 0; s < 2; s++) {
            acc[s][0] = bi[s][0]; acc[s][1] = bi[s][1];
            acc[s][2] = bi[s][0]; acc[s][3] = bi[s][1];
        }

        #pragma unroll
        for (int k = 0; k < 4; k++) {
            int ak = 16 * k + ((sel >> 1) << 3);
            uint32_t a0, a1, a2, a3;
            LDSM4(a0, a1, a2, a3, sm_addr(&Ahh[ar][ak]));
            MMA_F16(acc[0][0],acc[0][1],acc[0][2],acc[0][3], a0,a1,a2,a3, bh[k][0],bh[k][1]);
            MMA_F16(acc[1][0],acc[1][1],acc[1][2],acc[1][3], a0,a1,a2,a3, bh[k][2],bh[k][3]);
        }
        __syncthreads();

        long rg0 = ti * 16 + (lane >> 2);
        long rg1 = rg0 + 8;
        #pragma unroll
        for (int s = 0; s < 2; s++) {
            int cs = c0 + s * 8 + (lane & 3) * 2;
            *(__half2*)(outH + rg0 * 64 + cs) = __floats2half2_rn(acc[s][0], acc[s][1]);
            *(__half2*)(outH + rg1 * 64 + cs) = __floats2half2_rn(acc[s][2], acc[s][3]);
        }
    }
}

// ---------------- edge encoder: fp16 A + fp16 W single-pass, direct scatter ---
template<int TILES>
__global__ __launch_bounds__(128) void k_gemm_edge(
    const float* __restrict__ A,
    const float* __restrict__ W, const float* __restrict__ bias,
    __half* __restrict__ outH, const int* __restrict__ pos)
{
    __shared__ __align__(16) char smraw[9216];
    __half (*Wh)[72]  = (__half(*)[72])smraw;
    __half (*Ahh)[72] = (__half(*)[72])smraw;

    int t = threadIdx.x;
    int w = t >> 5, lane = t & 31;
    int tr = lane & 7, sel = lane >> 3;

    for (int i = t; i < 4096; i += 128) {
        int k = i >> 6, n = i & 63;
        Wh[n][k] = __float2half_rn(W[i]);
    }
    __syncthreads();

    int c0 = w * 16;
    uint32_t bh[4][4];
    {
        int bn = c0 + tr + ((sel & 2) << 2);
        #pragma unroll
        for (int k = 0; k < 4; k++) {
            int bk = 16 * k + ((sel & 1) << 3);
            LDSM4(bh[k][0], bh[k][1], bh[k][2], bh[k][3], sm_addr(&Wh[bn][bk]));
        }
    }
    __syncthreads();

    float bi[2][2];
    #pragma unroll
    for (int s = 0; s < 2; s++) {
        int cs = c0 + s * 8 + (lane & 3) * 2;
        bi[s][0] = __ldg(&bias[cs]);
        bi[s][1] = __ldg(&bias[cs + 1]);
    }

    int r = t >> 3, q = t & 7;
    int ar = tr + ((sel & 1) << 3);

    long ti0 = (long)blockIdx.x * TILES;
    float4 pfa = __ldcs((const float4*)(A + (ti0 * 16 + r) * 64 + q * 8));
    float4 pfb = __ldcs((const float4*)(A + (ti0 * 16 + r) * 64 + q * 8 + 4));

    for (int it = 0; it < TILES; it++) {
        long ti = ti0 + it;
        {
            uint4 hv;
            hv.x = hf2u(pfa.x, pfa.y); hv.y = hf2u(pfa.z, pfa.w);
            hv.z = hf2u(pfb.x, pfb.y); hv.w = hf2u(pfb.z, pfb.w);
            *(uint4*)&Ahh[r][q * 8] = hv;
        }
        __syncthreads();

        if (it + 1 < TILES) {
            pfa = __ldcs((const float4*)(A + ((ti + 1) * 16 + r) * 64 + q * 8));
            pfb = __ldcs((const float4*)(A + ((ti + 1) * 16 + r) * 64 + q * 8 + 4));
        }

        float acc[2][4];
        #pragma unroll
        for (int s = 0; s < 2; s++) {
            acc[s][0] = bi[s][0]; acc[s][1] = bi[s][1];
            acc[s][2] = bi[s][0]; acc[s][3] = bi[s][1];
        }

        #pragma unroll
        for (int k = 0; k < 4; k++) {
            int ak = 16 * k + ((sel >> 1) << 3);
            uint32_t a0, a1, a2, a3;
            LDSM4(a0, a1, a2, a3, sm_addr(&Ahh[ar][ak]));
            MMA_F16(acc[0][0],acc[0][1],acc[0][2],acc[0][3], a0,a1,a2,a3, bh[k][0],bh[k][1]);
            MMA_F16(acc[1][0],acc[1][1],acc[1][2],acc[1][3], a0,a1,a2,a3, bh[k][2],bh[k][3]);
        }
        __syncthreads();

        long row0 = ti * 16 + (lane >> 2);
        long p0 = (long)__ldg(&pos[row0]);
        long p1 = (long)__ldg(&pos[row0 + 8]);
        #pragma unroll
        for (int s = 0; s < 2; s++) {
            int cs = c0 + s * 8 + (lane & 3) * 2;
            *(__half2*)(outH + p0 * 64 + cs) = __floats2half2_rn(acc[s][0], acc[s][1]);
            *(__half2*)(outH + p1 * 64 + cs) = __floats2half2_rn(acc[s][2], acc[s][3]);
        }
    }
}

// ---------------- final linear: fp16 A single-pass, W fp16 hi/lo, fp32 out ----
template<int TILES>
__global__ __launch_bounds__(128) void k_gemm_h16(
    const __half* __restrict__ A,
    const float* __restrict__ W, const float* __restrict__ bias,
    float* __restrict__ outF)
{
    __shared__ __align__(16) char smraw[18432];
    __half (*Wh)[72]  = (__half(*)[72])smraw;
    __half (*Wl)[72]  = (__half(*)[72])(smraw + 9216);
    __half (*Ahh)[72] = (__half(*)[72])smraw;

    int t = threadIdx.x;
    int w = t >> 5, lane = t & 31;
    int tr = lane & 7, sel = lane >> 3;

    for (int i = t; i < 4096; i += 128) {
        int k = i >> 6, n = i & 63;
        float wv = W[i];
        __half h = __float2half_rn(wv);
        Wh[n][k] = h;
        Wl[n][k] = __float2half_rn(wv - __half2float(h));
    }
    __syncthreads();

    int c0 = w * 16;
    uint32_t bh[4][4], bl[4][4];
    {
        int bn = c0 + tr + ((sel & 2) << 2);
        #pragma unroll
        for (int k = 0; k < 4; k++) {
            int bk = 16 * k + ((sel & 1) << 3);
            LDSM4(bh[k][0], bh[k][1], bh[k][2], bh[k][3], sm_addr(&Wh[bn][bk]));
            LDSM4(bl[k][0], bl[k][1], bl[k][2], bl[k][3], sm_addr(&Wl[bn][bk]));
        }
    }
    __syncthreads();

    float bi[2][2];
    #pragma unroll
    for (int s = 0; s < 2; s++) {
        int cs = c0 + s * 8 + (lane & 3) * 2;
        bi[s][0] = __ldg(&bias[cs]);
        bi[s][1] = __ldg(&bias[cs + 1]);
    }

    int r = t >> 3, q = t & 7;
    int ar = tr + ((sel & 1) << 3);

    long ti0 = (long)blockIdx.x * TILES;
    uint4 pfu = __ldcs((const uint4*)(A + (ti0 * 16 + r) * 64 + q * 8));

    for (int it = 0; it < TILES; it++) {
        long ti = ti0 + it;
        *(uint4*)&Ahh[r][q * 8] = pfu;
        __syncthreads();

        if (it + 1 < TILES)
            pfu = __ldcs((const uint4*)(A + ((ti + 1) * 16 + r) * 64 + q * 8));

        float acc[2][4];
        #pragma unroll
        for (int s = 0; s < 2; s++) {
            acc[s][0] = bi[s][0]; acc[s][1] = bi[s][1];
            acc[s][2] = bi[s][0]; acc[s][3] = bi[s][1];
        }

        #pragma unroll
        for (int k = 0; k < 4; k++) {
            int ak = 16 * k + ((sel >> 1) << 3);
            uint32_t a0, a1, a2, a3;
            LDSM4(a0, a1, a2, a3, sm_addr(&Ahh[ar][ak]));
            MMA_F16(acc[0][0],acc[0][1],acc[0][2],acc[0][3], a0,a1,a2,a3, bh[k][0],bh[k][1]);
            MMA_F16(acc[0][0],acc[0][1],acc[0][2],acc[0][3], a0,a1,a2,a3, bl[k][0],bl[k][1]);
            MMA_F16(acc[1][0],acc[1][1],acc[1][2],acc[1][3], a0,a1,a2,a3, bh[k][2],bh[k][3]);
            MMA_F16(acc[1][0],acc[1][1],acc[1][2],acc[1][3], a0,a1,a2,a3, bl[k][2],bl[k][3]);
        }
        __syncthreads();

        long rg0 = ti * 16 + (lane >> 2);
        long rg1 = rg0 + 8;
        #pragma unroll
        for (int s = 0; s < 2; s++) {
            int cs = c0 + s * 8 + (lane & 3) * 2;
            *(float2*)(outF + rg0 * 64 + cs) = make_float2(acc[s][0], acc[s][1]);
            *(float2*)(outF + rg1 * 64 + cs) = make_float2(acc[s][2], acc[s][3]);
        }
    }
}

// ---------------- conv GEMM (u fp16 exact, W fp16 hi/lo) + LN epilogue --------
template<bool RES, bool FINAL, int TILES>
__global__ __launch_bounds__(128) void k_gemm_conv(
    const __half* __restrict__ U,
    const float* __restrict__ W, const float* __restrict__ bias,
    const float* __restrict__ hres,
    const float* __restrict__ gamma, const float* __restrict__ beta,
    float* __restrict__ houtF, __half* __restrict__ zoutH)
{
    __shared__ __align__(16) char smraw[18432];
    __half (*Wh)[72]  = (__half(*)[72])smraw;
    __half (*Wl)[72]  = (__half(*)[72])(smraw + 9216);
    __half (*Ahh)[72] = (__half(*)[72])smraw;
    float  (*OSf)[72] = (float(*)[72]) (smraw + 2304);

    int t = threadIdx.x;
    int w = t >> 5, lane = t & 31;
    int tr = lane & 7, sel = lane >> 3;

    for (int i = t; i < 4096; i += 128) {
        int k = i >> 6, n = i & 63;
        float wv = W[i];
        __half h = __float2half_rn(wv);
        Wh[n][k] = h;
        Wl[n][k] = __float2half_rn(wv - __half2float(h));
    }
    __syncthreads();

    int c0 = w * 16;
    uint32_t bh[4][4], bl[4][4];
    {
        int bn = c0 + tr + ((sel & 2) << 2);
        #pragma unroll
        for (int k = 0; k < 4; k++) {
            int bk = 16 * k + ((sel & 1) << 3);
            LDSM4(bh[k][0], bh[k][1], bh[k][2], bh[k][3], sm_addr(&Wh[bn][bk]));
            LDSM4(bl[k][0], bl[k][1], bl[k][2], bl[k][3], sm_addr(&Wl[bn][bk]));
        }
    }
    __syncthreads();

    float bi[2][2];
    #pragma unroll
    for (int s = 0; s < 2; s++) {
        int cs = c0 + s * 8 + (lane & 3) * 2;
        bi[s][0] = __ldg(&bias[cs]);
        bi[s][1] = __ldg(&bias[cs + 1]);
    }

    int r = t >> 3, q = t & 7;
    int ar = tr + ((sel & 1) << 3);

    float4 ga0 = __ldg((const float4*)(gamma + q * 8));
    float4 ga1 = __ldg((const float4*)(gamma + q * 8 + 4));
    float4 be0 = __ldg((const float4*)(beta  + q * 8));
    float4 be1 = __ldg((const float4*)(beta  + q * 8 + 4));

    long ti0 = (long)blockIdx.x * TILES;
    uint4 pfu = __ldcs((const uint4*)(U + (ti0 * 16 + r) * 64 + q * 8));

    for (int it = 0; it < TILES; it++) {
        long ti = ti0 + it;
        *(uint4*)&Ahh[r][q * 8] = pfu;
        __syncthreads();

        if (it + 1 < TILES)
            pfu = __ldcs((const uint4*)(U + ((ti + 1) * 16 + r) * 64 + q * 8));

        float acc[2][4];
        #pragma unroll
        for (int s = 0; s < 2; s++) {
            acc[s][0] = bi[s][0]; acc[s][1] = bi[s][1];
            acc[s][2] = bi[s][0]; acc[s][3] = bi[s][1];
        }

        #pragma unroll
        for (int k = 0; k < 4; k++) {
            int ak = 16 * k + ((sel >> 1) << 3);
            uint32_t a0, a1, a2, a3;
            LDSM4(a0, a1, a2, a3, sm_addr(&Ahh[ar][ak]));
            MMA_F16(acc[0][0],acc[0][1],acc[0][2],acc[0][3], a0,a1,a2,a3, bh[k][0],bh[k][1]);
            MMA_F16(acc[0][0],acc[0][1],acc[0][2],acc[0][3], a0,a1,a2,a3, bl[k][0],bl[k][1]);
            MMA_F16(acc[1][0],acc[1][1],acc[1][2],acc[1][3], a0,a1,a2,a3, bh[k][2],bh[k][3]);
            MMA_F16(acc[1][0],acc[1][1],acc[1][2],acc[1][3], a0,a1,a2,a3, bl[k][2],bl[k][3]);
        }
        __syncthreads();

        {
            int r0 = lane >> 2, r1 = r0 + 8;
            #pragma unroll
            for (int s = 0; s < 2; s++) {
                int cs = c0 + s * 8 + (lane & 3) * 2;
                *(float2*)&OSf[r0][cs] = make_float2(acc[s][0], acc[s][1]);
                *(float2*)&OSf[r1][cs] = make_float2(acc[s][2], acc[s][3]);
            }
        }
        __syncthreads();

        {
            long row = ti * 16 + r;
            float4 va = *(float4*)&OSf[r][q * 8];
            float4 vb = *(float4*)&OSf[r][q * 8 + 4];
            if (RES) {
                float4 ha = __ldcs((const float4*)(hres + row * 64 + q * 8));
                float4 hb = __ldcs((const float4*)(hres + row * 64 + q * 8 + 4));
                va.x += ha.x; va.y += ha.y; va.z += ha.z; va.w += ha.w;
                vb.x += hb.x; vb.y += hb.y; vb.z += hb.z; vb.w += hb.w;
            }
            float s = va.x + va.y + va.z + va.w + vb.x + vb.y + vb.z + vb.w;
            float ss = va.x*va.x + va.y*va.y + va.z*va.z + va.w*va.w
                     + vb.x*vb.x + vb.y*vb.y + vb.z*vb.z + vb.w*vb.w;
            #pragma unroll
            for (int m = 1; m < 8; m <<= 1) {
                s  += __shfl_xor_sync(0xffffffffu, s,  m);
                ss += __shfl_xor_sync(0xffffffffu, ss, m);
            }
            float mu = s * (1.0f / 64.0f);
            float var = fmaxf(ss * (1.0f / 64.0f) - mu * mu, 0.0f);
            float rs = rsqrtf(var + 1e-5f);
            float z0 = fmaxf(fmaf((va.x - mu) * rs, ga0.x, be0.x), 0.f);
            float z1 = fmaxf(fmaf((va.y - mu) * rs, ga0.y, be0.y), 0.f);
            float z2 = fmaxf(fmaf((va.z - mu) * rs, ga0.z, be0.z), 0.f);
            float z3 = fmaxf(fmaf((va.w - mu) * rs, ga0.w, be0.w), 0.f);
            float z4 = fmaxf(fmaf((vb.x - mu) * rs, ga1.x, be1.x), 0.f);
            float z5 = fmaxf(fmaf((vb.y - mu) * rs, ga1.y, be1.y), 0.f);
            float z6 = fmaxf(fmaf((vb.z - mu) * rs, ga1.z, be1.z), 0.f);
            float z7 = fmaxf(fmaf((vb.w - mu) * rs, ga1.w, be1.w), 0.f);
            if (!FINAL) {
                *(float4*)(houtF + row * 64 + q * 8)     = va;
                *(float4*)(houtF + row * 64 + q * 8 + 4) = vb;
            }
            uint4 zv;
            zv.x = hf2u(z0, z1); zv.y = hf2u(z2, z3);
            zv.z = hf2u(z4, z5); zv.w = hf2u(z6, z7);
            *(uint4*)(zoutH + row * 64 + q * 8) = zv;
        }
    }
}

// ---------------- aggregation: u = softmax-aggr + z (R8-proven form) ---------
#define AGG_GRID 1563
__global__ __launch_bounds__(256) void k_agg_lite(
    const __half2* __restrict__ z2, const float* __restrict__ tptr,
    __half2* __restrict__ uout)
{
    int t = threadIdx.x;
    int w = t >> 5, l = t & 31;
    float tv = __ldg(tptr);
    float kf = tv * 1.44269504f;
    const __half2 zero2 = __float2half2_rn(0.f);
    const __half2 eps2  = __float2half2_rn(1e-7f);
    const __half2* e2 = (const __half2*)g_eh;

    #pragma unroll 1
    for (int round = 0; round < 8; round++) {
        int node = round * (AGG_GRID * 8) + blockIdx.x * 8 + w;
        if (node >= NN) continue;

        int beg = g_offs[node], end = g_offs[node + 1];
        float d0 = 0.f, d1 = 0.f, s0 = 0.f, s1 = 0.f;
        int p = beg;
        for (; p + 4 <= end; p += 4) {
            __half2 ea = __ldcs(&e2[(size_t)p * 32 + l]);
            __half2 eb = __ldcs(&e2[(size_t)(p + 1) * 32 + l]);
            __half2 ec = __ldcs(&e2[(size_t)(p + 2) * 32 + l]);
            __half2 ed = __ldcs(&e2[(size_t)(p + 3) * 32 + l]);
            int i0 = __ldg(&g_srcn[p]);
            int i1 = __ldg(&g_srcn[p + 1]);
            int i2 = __ldg(&g_srcn[p + 2]);
            int i3 = __ldg(&g_srcn[p + 3]);
            __half2 za = __ldg(&z2[(size_t)i0 * 32 + l]);
            __half2 zb = __ldg(&z2[(size_t)i1 * 32 + l]);
            __half2 zc = __ldg(&z2[(size_t)i2 * 32 + l]);
            __half2 zd = __ldg(&z2[(size_t)i3 * 32 + l]);
            __half2 ma = __hadd2(__hmax2(__hadd2(ea, za), zero2), eps2);
            __half2 mb = __hadd2(__hmax2(__hadd2(eb, zb), zero2), eps2);
            __half2 mc = __hadd2(__hmax2(__hadd2(ec, zc), zero2), eps2);
            __half2 md = __hadd2(__hmax2(__hadd2(ed, zd), zero2), eps2);
            float m0, m1, x0, x1;
            m0 = __low2float(ma); m1 = __high2float(ma);
            x0 = ex2f(m0 * kf); x1 = ex2f(m1 * kf);
            d0 += x0; s0 = fmaf(x0, m0, s0);
            d1 += x1; s1 = fmaf(x1, m1, s1);
            m0 = __low2float(mb); m1 = __high2float(mb);
            x0 = ex2f(m0 * kf); x1 = ex2f(m1 * kf);
            d0 += x0; s0 = fmaf(x0, m0, s0);
            d1 += x1; s1 = fmaf(x1, m1, s1);
            m0 = __low2float(mc); m1 = __high2float(mc);
            x0 = ex2f(m0 * kf); x1 = ex2f(m1 * kf);
            d0 += x0; s0 = fmaf(x0, m0, s0);
            d1 += x1; s1 = fmaf(x1, m1, s1);
            m0 = __low2float(md); m1 = __high2float(md);
            x0 = ex2f(m0 * kf); x1 = ex2f(m1 * kf);
            d0 += x0; s0 = fmaf(x0, m0, s0);
            d1 += x1; s1 = fmaf(x1, m1, s1);
        }
        for (; p < end; p++) {
            __half2 ef = __ldcs(&e2[(size_t)p * 32 + l]);
            int si = __ldg(&g_srcn[p]);
            __half2 zv = __ldg(&z2[(size_t)si * 32 + l]);
            __half2 ma = __hadd2(__hmax2(__hadd2(ef, zv), zero2), eps2);
            float m0 = __low2float(ma), m1 = __high2float(ma);
            float x0 = ex2f(m0 * kf), x1 = ex2f(m1 * kf);
            d0 += x0; s0 = fmaf(x0, m0, s0);
            d1 += x1; s1 = fmaf(x1, m1, s1);
        }

        float2 zn = __half22float2(z2[(size_t)node * 32 + l]);
        float u0 = __fdividef(s0, d0 + 1e-16f) + zn.x;
        float u1 = __fdividef(s1, d1 + 1e-16f) + zn.y;
        uout[(size_t)node * 32 + l] = __floats2half2_rn(u0, u1);
    }
}

// ---------------- launch ----------------
extern "C" void kernel_launch(void* const* d_in, const int* in_sizes, int n_in,
                              void* d_out, int out_size)
{
    const float* x         = (const float*)d_in[0];
    const float* edge_attr = (const float*)d_in[1];
    const int*   ei        = (const int*)d_in[2];
    const float* W_ne      = (const float*)d_in[3];
    const float* b_ne      = (const float*)d_in[4];
    const float* W_ee      = (const float*)d_in[5];
    const float* b_ee      = (const float*)d_in[6];
    const float* W_conv    = (const float*)d_in[7];
    const float* b_conv    = (const float*)d_in[8];
    const float* tarr      = (const float*)d_in[9];
    const float* gamma     = (const float*)d_in[10];
    const float* beta      = (const float*)d_in[11];
    const float* W_lin     = (const float*)d_in[12];
    const float* b_lin     = (const float*)d_in[13];
    float* out = (float*)d_out;

    float *p_hA, *p_hB;
    __half *p_eh, *p_zh0, *p_zh1, *p_u;
    int *p_pos;
    cudaGetSymbolAddress((void**)&p_eh,  g_eh);
    cudaGetSymbolAddress((void**)&p_zh0, g_zh0);
    cudaGetSymbolAddress((void**)&p_zh1, g_zh1);
    cudaGetSymbolAddress((void**)&p_u,   g_u);
    cudaGetSymbolAddress((void**)&p_hA,  g_hA);
    cudaGetSymbolAddress((void**)&p_hB,  g_hB);
    cudaGetSymbolAddress((void**)&p_pos, g_pos);

    const int NB_E  = (NE + 255) / 256;
    const int NB_S  = (NN + 1023) / 1024;
    const int NB_SC = (NN + 255) / 256;

    // CSR
    k_hist  <<<NB_E, 256>>>(ei);
    k_scan1 <<<NB_S, 1024>>>();
    k_scan23<<<NB_SC, 256>>>();
    k_scatter<<<NB_E, 256>>>(ei);
    // encoders
    k_gemm_edge<16><<<6250, 128>>>(edge_attr, W_ee, b_ee, p_eh, p_pos);
    k_gemm_node<10><<<625, 128>>>(x, W_ne, b_ne, p_zh0);

    // layer 0
    k_agg_lite<<<AGG_GRID, 256>>>((const __half2*)p_zh0, tarr, (__half2*)p_u);
    k_gemm_conv<false, false, 10><<<625, 128>>>(p_u, W_conv, b_conv, nullptr,
        gamma + 64, beta + 64, p_hB, p_zh1);
    // layer 1
    k_agg_lite<<<AGG_GRID, 256>>>((const __half2*)p_zh1, tarr + 1, (__half2*)p_u);
    k_gemm_conv<true, false, 10><<<625, 128>>>(p_u, W_conv + 4096, b_conv + 64, p_hB,
        gamma + 128, beta + 128, p_hA, p_zh0);
    // layer 2
    k_agg_lite<<<AGG_GRID, 256>>>((const __half2*)p_zh0, tarr + 2, (__half2*)p_u);
    k_gemm_conv<true, false, 10><<<625, 128>>>(p_u, W_conv + 8192, b_conv + 128, p_hA,
        gamma + 192, beta + 192, p_hB, p_zh1);
    // layer 3 (FINAL: z fp16 only, LN with gamma0/beta0)
    k_agg_lite<<<AGG_GRID, 256>>>((const __half2*)p_zh1, tarr + 3, (__half2*)p_u);
    k_gemm_conv<true, true, 10><<<625, 128>>>(p_u, W_conv + 12288, b_conv + 192, p_hB,
        gamma, beta, nullptr, p_zh0);

    // final linear (fp16 z input)
    k_gemm_h16<10><<<625, 128>>>(p_zh0, W_lin, b_lin, out);
}

// round 15
// speedup vs baseline: 1.0426x; 1.0264x over previous
#include <cuda_runtime.h>
#include <cuda_fp16.h>
#include <cuda_bf16.h>
#include <cstdint>

#define NN 100000
#define NE 1600000

// ---------------- device scratch ----------------
__device__ __half g_eh[(size_t)NE * 64];    // edge features fp16, CSR order
__device__ __half g_zh0[(size_t)NN * 64];
__device__ __half g_zh1[(size_t)NN * 64];
__device__ __half g_u[(size_t)NN * 64];
__device__ __half g_hA[(size_t)NN * 64];    // residual h, fp16
__device__ __half g_hB[(size_t)NN * 64];
__device__ int    g_srcn[NE];
__device__ int    g_pos[NE];
__device__ int    g_rank[NE];
__device__ int    g_offs[NN + 1];
__device__ int    g_deg[NN];
__device__ int    g_bsum[128];

// ---------------- CSR build ----------------
__global__ void k_scan1() {
    int t = threadIdx.x;
    int idx = blockIdx.x * 1024 + t;
    int v = (idx < NN) ? g_deg[idx] : 0;
    if (idx < NN) g_deg[idx] = 0;
    int x = v;
    int lane = t & 31, w = t >> 5;
    #pragma unroll
    for (int o = 1; o < 32; o <<= 1) {
        int y = __shfl_up_sync(0xffffffffu, x, o);
        if (lane >= o) x += y;
    }
    __shared__ int ws[32];
    if (lane == 31) ws[w] = x;
    __syncthreads();
    if (w == 0) {
        int y = ws[lane];
        #pragma unroll
        for (int o = 1; o < 32; o <<= 1) {
            int z2 = __shfl_up_sync(0xffffffffu, y, o);
            if (lane >= o) y += z2;
        }
        ws[lane] = y;
    }
    __syncthreads();
    int incl = x + (w > 0 ? ws[w - 1] : 0);
    if (idx < NN) g_offs[idx] = incl - v;
    if (t == 1023) g_bsum[blockIdx.x] = incl;
}
__global__ __launch_bounds__(256) void k_scan23() {
    __shared__ int bs[128];
    __shared__ int ws[4];
    int t = threadIdx.x;
    const int nb = (NN + 1023) >> 10;
    int v = 0, x = 0;
    int lane = t & 31, w = t >> 5;
    if (t < 128) {
        v = (t < nb) ? g_bsum[t] : 0;
        x = v;
        #pragma unroll
        for (int o = 1; o < 32; o <<= 1) {
            int y = __shfl_up_sync(0xffffffffu, x, o);
            if (lane >= o) x += y;
        }
        if (lane == 31) ws[w] = x;
    }
    __syncthreads();
    if (t < 128) {
        int add = 0;
        if (w == 1) add = ws[0];
        else if (w == 2) add = ws[0] + ws[1];
        else if (w == 3) add = ws[0] + ws[1] + ws[2];
        bs[t] = x + add - v;
    }
    __syncthreads();
    int idx = blockIdx.x * 256 + t;
    if (idx < NN) g_offs[idx] += bs[idx >> 10];
    if (idx == 0) g_offs[NN] = NE;
}
__global__ void k_scatter(const int* __restrict__ ei) {
    int i = blockIdx.x * blockDim.x + threadIdx.x;
    if (i < NE) {
        int d = ei[NE + i];
        int p = g_offs[d] + g_rank[i];
        g_srcn[p] = ei[i];
        g_pos[i] = p;
    }
}

// ---------------- GEMM plumbing ----------------
#define LDSM4(R0,R1,R2,R3,ADDR) \
    asm volatile("ldmatrix.sync.aligned.m8n8.x4.shared.b16 {%0,%1,%2,%3}, [%4];" \
        : "=r"(R0),"=r"(R1),"=r"(R2),"=r"(R3) : "r"(ADDR))
#define MMA_F16(C0,C1,C2,C3,A0,A1,A2,A3,B0,B1) \
    asm volatile("mma.sync.aligned.m16n8k16.row.col.f32.f16.f16.f32 " \
        "{%0,%1,%2,%3},{%4,%5,%6,%7},{%8,%9},{%0,%1,%2,%3};" \
        : "+f"(C0),"+f"(C1),"+f"(C2),"+f"(C3) \
        : "r"(A0),"r"(A1),"r"(A2),"r"(A3),"r"(B0),"r"(B1))

__device__ __forceinline__ uint32_t sm_addr(const void* p) {
    return (uint32_t)__cvta_generic_to_shared(p);
}
__device__ __forceinline__ uint32_t hf2u(float a, float b) {
    __half2 v = __floats2half2_rn(a, b);
    return *(uint32_t*)&v;
}
__device__ __forceinline__ float ex2f(float x) {
    float r; asm("ex2.approx.f32 %0, %1;" : "=f"(r) : "f"(x)); return r;
}

// ---------------- node encoder (blocks 0..624) + edge histogram (rest) -------
// Both depend only on kernel inputs -> merged so they execute concurrently.
template<int TILES>
__global__ __launch_bounds__(128) void k_node_hist(
    const float* __restrict__ A,
    const float* __restrict__ W, const float* __restrict__ bias,
    __half* __restrict__ outH, const int* __restrict__ ei)
{
    __shared__ __align__(16) char smraw[9216];

    if (blockIdx.x >= 625) {
        // histogram part: one element per thread
        int i = (blockIdx.x - 625) * 128 + threadIdx.x;
        if (i < NE) g_rank[i] = atomicAdd(&g_deg[ei[NE + i]], 1);
        return;
    }

    __half (*Wh)[72]  = (__half(*)[72])smraw;
    __half (*Ahh)[72] = (__half(*)[72])smraw;

    int t = threadIdx.x;
    int w = t >> 5, lane = t & 31;
    int tr = lane & 7, sel = lane >> 3;

    for (int i = t; i < 4096; i += 128) {
        int k = i >> 6, n = i & 63;
        Wh[n][k] = __float2half_rn(W[i]);
    }
    __syncthreads();

    int c0 = w * 16;
    uint32_t bh[4][4];
    {
        int bn = c0 + tr + ((sel & 2) << 2);
        #pragma unroll
        for (int k = 0; k < 4; k++) {
            int bk = 16 * k + ((sel & 1) << 3);
            LDSM4(bh[k][0], bh[k][1], bh[k][2], bh[k][3], sm_addr(&Wh[bn][bk]));
        }
    }
    __syncthreads();

    float bi[2][2];
    #pragma unroll
    for (int s = 0; s < 2; s++) {
        int cs = c0 + s * 8 + (lane & 3) * 2;
        bi[s][0] = __ldg(&bias[cs]);
        bi[s][1] = __ldg(&bias[cs + 1]);
    }

    int r = t >> 3, q = t & 7;
    int ar = tr + ((sel & 1) << 3);

    long ti0 = (long)blockIdx.x * TILES;
    float4 pfa = __ldcs((const float4*)(A + (ti0 * 16 + r) * 64 + q * 8));
    float4 pfb = __ldcs((const float4*)(A + (ti0 * 16 + r) * 64 + q * 8 + 4));

    for (int it = 0; it < TILES; it++) {
        long ti = ti0 + it;
        {
            uint4 hv;
            hv.x = hf2u(pfa.x, pfa.y); hv.y = hf2u(pfa.z, pfa.w);
            hv.z = hf2u(pfb.x, pfb.y); hv.w = hf2u(pfb.z, pfb.w);
            *(uint4*)&Ahh[r][q * 8] = hv;
        }
        __syncthreads();

        if (it + 1 < TILES) {
            pfa = __ldcs((const float4*)(A + ((ti + 1) * 16 + r) * 64 + q * 8));
            pfb = __ldcs((const float4*)(A + ((ti + 1) * 16 + r) * 64 + q * 8 + 4));
        }

        float acc[2][4];
        #pragma unroll
        for (int s = 0; s < 2; s++) {
            acc[s][0] = bi[s][0]; acc[s][1] = bi[s][1];
            acc[s][2] = bi[s][0]; acc[s][3] = bi[s][1];
        }

        #pragma unroll
        for (int k = 0; k < 4; k++) {
            int ak = 16 * k + ((sel >> 1) << 3);
            uint32_t a0, a1, a2, a3;
            LDSM4(a0, a1, a2, a3, sm_addr(&Ahh[ar][ak]));
            MMA_F16(acc[0][0],acc[0][1],acc[0][2],acc[0][3], a0,a1,a2,a3, bh[k][0],bh[k][1]);
            MMA_F16(acc[1][0],acc[1][1],acc[1][2],acc[1][3], a0,a1,a2,a3, bh[k][2],bh[k][3]);
        }
        __syncthreads();

        long rg0 = ti * 16 + (lane >> 2);
        long rg1 = rg0 + 8;
        #pragma unroll
        for (int s = 0; s < 2; s++) {
            int cs = c0 + s * 8 + (lane & 3) * 2;
            *(__half2*)(outH + rg0 * 64 + cs) = __floats2half2_rn(acc[s][0], acc[s][1]);
            *(__half2*)(outH + rg1 * 64 + cs) = __floats2half2_rn(acc[s][2], acc[s][3]);
        }
    }
}

// ---------------- edge encoder: fp16 A + fp16 W single-pass, direct scatter ---
template<int TILES>
__global__ __launch_bounds__(128) void k_gemm_edge(
    const float* __restrict__ A,
    const float* __restrict__ W, const float* __restrict__ bias,
    __half* __restrict__ outH, const int* __restrict__ pos)
{
    __shared__ __align__(16) char smraw[9216];
    __half (*Wh)[72]  = (__half(*)[72])smraw;
    __half (*Ahh)[72] = (__half(*)[72])smraw;

    int t = threadIdx.x;
    int w = t >> 5, lane = t & 31;
    int tr = lane & 7, sel = lane >> 3;

    for (int i = t; i < 4096; i += 128) {
        int k = i >> 6, n = i & 63;
        Wh[n][k] = __float2half_rn(W[i]);
    }
    __syncthreads();

    int c0 = w * 16;
    uint32_t bh[4][4];
    {
        int bn = c0 + tr + ((sel & 2) << 2);
        #pragma unroll
        for (int k = 0; k < 4; k++) {
            int bk = 16 * k + ((sel & 1) << 3);
            LDSM4(bh[k][0], bh[k][1], bh[k][2], bh[k][3], sm_addr(&Wh[bn][bk]));
        }
    }
    __syncthreads();

    float bi[2][2];
    #pragma unroll
    for (int s = 0; s < 2; s++) {
        int cs = c0 + s * 8 + (lane & 3) * 2;
        bi[s][0] = __ldg(&bias[cs]);
        bi[s][1] = __ldg(&bias[cs + 1]);
    }

    int r = t >> 3, q = t & 7;
    int ar = tr + ((sel & 1) << 3);

    long ti0 = (long)blockIdx.x * TILES;
    float4 pfa = __ldcs((const float4*)(A + (ti0 * 16 + r) * 64 + q * 8));
    float4 pfb = __ldcs((const float4*)(A + (ti0 * 16 + r) * 64 + q * 8 + 4));

    for (int it = 0; it < TILES; it++) {
        long ti = ti0 + it;
        {
            uint4 hv;
            hv.x = hf2u(pfa.x, pfa.y); hv.y = hf2u(pfa.z, pfa.w);
            hv.z = hf2u(pfb.x, pfb.y); hv.w = hf2u(pfb.z, pfb.w);
            *(uint4*)&Ahh[r][q * 8] = hv;
        }
        __syncthreads();

        if (it + 1 < TILES) {
            pfa = __ldcs((const float4*)(A + ((ti + 1) * 16 + r) * 64 + q * 8));
            pfb = __ldcs((const float4*)(A + ((ti + 1) * 16 + r) * 64 + q * 8 + 4));
        }

        float acc[2][4];
        #pragma unroll
        for (int s = 0; s < 2; s++) {
            acc[s][0] = bi[s][0]; acc[s][1] = bi[s][1];
            acc[s][2] = bi[s][0]; acc[s][3] = bi[s][1];
        }

        #pragma unroll
        for (int k = 0; k < 4; k++) {
            int ak = 16 * k + ((sel >> 1) << 3);
            uint32_t a0, a1, a2, a3;
            LDSM4(a0, a1, a2, a3, sm_addr(&Ahh[ar][ak]));
            MMA_F16(acc[0][0],acc[0][1],acc[0][2],acc[0][3], a0,a1,a2,a3, bh[k][0],bh[k][1]);
            MMA_F16(acc[1][0],acc[1][1],acc[1][2],acc[1][3], a0,a1,a2,a3, bh[k][2],bh[k][3]);
        }
        __syncthreads();

        long row0 = ti * 16 + (lane >> 2);
        long p0 = (long)__ldg(&pos[row0]);
        long p1 = (long)__ldg(&pos[row0 + 8]);
        #pragma unroll
        for (int s = 0; s < 2; s++) {
            int cs = c0 + s * 8 + (lane & 3) * 2;
            *(__half2*)(outH + p0 * 64 + cs) = __floats2half2_rn(acc[s][0], acc[s][1]);
            *(__half2*)(outH + p1 * 64 + cs) = __floats2half2_rn(acc[s][2], acc[s][3]);
        }
    }
}

// ---------------- final linear: fp16 A single-pass, W fp16 hi/lo, fp32 out ----
template<int TILES>
__global__ __launch_bounds__(128) void k_gemm_h16(
    const __half* __restrict__ A,
    const float* __restrict__ W, const float* __restrict__ bias,
    float* __restrict__ outF)
{
    __shared__ __align__(16) char smraw[18432];
    __half (*Wh)[72]  = (__half(*)[72])smraw;
    __half (*Wl)[72]  = (__half(*)[72])(smraw + 9216);
    __half (*Ahh)[72] = (__half(*)[72])smraw;

    int t = threadIdx.x;
    int w = t >> 5, lane = t & 31;
    int tr = lane & 7, sel = lane >> 3;

    for (int i = t; i < 4096; i += 128) {
        int k = i >> 6, n = i & 63;
        float wv = W[i];
        __half h = __float2half_rn(wv);
        Wh[n][k] = h;
        Wl[n][k] = __float2half_rn(wv - __half2float(h));
    }
    __syncthreads();

    int c0 = w * 16;
    uint32_t bh[4][4], bl[4][4];
    {
        int bn = c0 + tr + ((sel & 2) << 2);
        #pragma unroll
        for (int k = 0; k < 4; k++) {
            int bk = 16 * k + ((sel & 1) << 3);
            LDSM4(bh[k][0], bh[k][1], bh[k][2], bh[k][3], sm_addr(&Wh[bn][bk]));
            LDSM4(bl[k][0], bl[k][1], bl[k][2], bl[k][3], sm_addr(&Wl[bn][bk]));
        }
    }
    __syncthreads();

    float bi[2][2];
    #pragma unroll
    for (int s = 0; s < 2; s++) {
        int cs = c0 + s * 8 + (lane & 3) * 2;
        bi[s][0] = __ldg(&bias[cs]);
        bi[s][1] = __ldg(&bias[cs + 1]);
    }

    int r = t >> 3, q = t & 7;
    int ar = tr + ((sel & 1) << 3);

    long ti0 = (long)blockIdx.x * TILES;
    uint4 pfu = __ldcs((const uint4*)(A + (ti0 * 16 + r) * 64 + q * 8));

    for (int it = 0; it < TILES; it++) {
        long ti = ti0 + it;
        *(uint4*)&Ahh[r][q * 8] = pfu;
        __syncthreads();

        if (it + 1 < TILES)
            pfu = __ldcs((const uint4*)(A + ((ti + 1) * 16 + r) * 64 + q * 8));

        float acc[2][4];
        #pragma unroll
        for (int s = 0; s < 2; s++) {
            acc[s][0] = bi[s][0]; acc[s][1] = bi[s][1];
            acc[s][2] = bi[s][0]; acc[s][3] = bi[s][1];
        }

        #pragma unroll
        for (int k = 0; k < 4; k++) {
            int ak = 16 * k + ((sel >> 1) << 3);
            uint32_t a0, a1, a2, a3;
            LDSM4(a0, a1, a2, a3, sm_addr(&Ahh[ar][ak]));
            MMA_F16(acc[0][0],acc[0][1],acc[0][2],acc[0][3], a0,a1,a2,a3, bh[k][0],bh[k][1]);
            MMA_F16(acc[0][0],acc[0][1],acc[0][2],acc[0][3], a0,a1,a2,a3, bl[k][0],bl[k][1]);
            MMA_F16(acc[1][0],acc[1][1],acc[1][2],acc[1][3], a0,a1,a2,a3, bh[k][2],bh[k][3]);
            MMA_F16(acc[1][0],acc[1][1],acc[1][2],acc[1][3], a0,a1,a2,a3, bl[k][2],bl[k][3]);
        }
        __syncthreads();

        long rg0 = ti * 16 + (lane >> 2);
        long rg1 = rg0 + 8;
        #pragma unroll
        for (int s = 0; s < 2; s++) {
            int cs = c0 + s * 8 + (lane & 3) * 2;
            *(float2*)(outF + rg0 * 64 + cs) = make_float2(acc[s][0], acc[s][1]);
            *(float2*)(outF + rg1 * 64 + cs) = make_float2(acc[s][2], acc[s][3]);
        }
    }
}

// ---------------- conv GEMM (u fp16 exact, W fp16 hi/lo) + LN epilogue --------
// Residual h is fp16 now. FINAL: writes z fp16 only.
template<bool RES, bool FINAL, int TILES>
__global__ __launch_bounds__(128) void k_gemm_conv(
    const __half* __restrict__ U,
    const float* __restrict__ W, const float* __restrict__ bias,
    const __half* __restrict__ hres,
    const float* __restrict__ gamma, const float* __restrict__ beta,
    __half* __restrict__ houtH, __half* __restrict__ zoutH)
{
    __shared__ __align__(16) char smraw[18432];
    __half (*Wh)[72]  = (__half(*)[72])smraw;
    __half (*Wl)[72]  = (__half(*)[72])(smraw + 9216);
    __half (*Ahh)[72] = (__half(*)[72])smraw;
    float  (*OSf)[72] = (float(*)[72]) (smraw + 2304);

    int t = threadIdx.x;
    int w = t >> 5, lane = t & 31;
    int tr = lane & 7, sel = lane >> 3;

    for (int i = t; i < 4096; i += 128) {
        int k = i >> 6, n = i & 63;
        float wv = W[i];
        __half h = __float2half_rn(wv);
        Wh[n][k] = h;
        Wl[n][k] = __float2half_rn(wv - __half2float(h));
    }
    __syncthreads();

    int c0 = w * 16;
    uint32_t bh[4][4], bl[4][4];
    {
        int bn = c0 + tr + ((sel & 2) << 2);
        #pragma unroll
        for (int k = 0; k < 4; k++) {
            int bk = 16 * k + ((sel & 1) << 3);
            LDSM4(bh[k][0], bh[k][1], bh[k][2], bh[k][3], sm_addr(&Wh[bn][bk]));
            LDSM4(bl[k][0], bl[k][1], bl[k][2], bl[k][3], sm_addr(&Wl[bn][bk]));
        }
    }
    __syncthreads();

    float bi[2][2];
    #pragma unroll
    for (int s = 0; s < 2; s++) {
        int cs = c0 + s * 8 + (lane & 3) * 2;
        bi[s][0] = __ldg(&bias[cs]);
        bi[s][1] = __ldg(&bias[cs + 1]);
    }

    int r = t >> 3, q = t & 7;
    int ar = tr + ((sel & 1) << 3);

    float4 ga0 = __ldg((const float4*)(gamma + q * 8));
    float4 ga1 = __ldg((const float4*)(gamma + q * 8 + 4));
    float4 be0 = __ldg((const float4*)(beta  + q * 8));
    float4 be1 = __ldg((const float4*)(beta  + q * 8 + 4));

    long ti0 = (long)blockIdx.x * TILES;
    uint4 pfu = __ldcs((const uint4*)(U + (ti0 * 16 + r) * 64 + q * 8));

    for (int it = 0; it < TILES; it++) {
        long ti = ti0 + it;
        *(uint4*)&Ahh[r][q * 8] = pfu;
        __syncthreads();

        if (it + 1 < TILES)
            pfu = __ldcs((const uint4*)(U + ((ti + 1) * 16 + r) * 64 + q * 8));

        float acc[2][4];
        #pragma unroll
        for (int s = 0; s < 2; s++) {
            acc[s][0] = bi[s][0]; acc[s][1] = bi[s][1];
            acc[s][2] = bi[s][0]; acc[s][3] = bi[s][1];
        }

        #pragma unroll
        for (int k = 0; k < 4; k++) {
            int ak = 16 * k + ((sel >> 1) << 3);
            uint32_t a0, a1, a2, a3;
            LDSM4(a0, a1, a2, a3, sm_addr(&Ahh[ar][ak]));
            MMA_F16(acc[0][0],acc[0][1],acc[0][2],acc[0][3], a0,a1,a2,a3, bh[k][0],bh[k][1]);
            MMA_F16(acc[0][0],acc[0][1],acc[0][2],acc[0][3], a0,a1,a2,a3, bl[k][0],bl[k][1]);
            MMA_F16(acc[1][0],acc[1][1],acc[1][2],acc[1][3], a0,a1,a2,a3, bh[k][2],bh[k][3]);
            MMA_F16(acc[1][0],acc[1][1],acc[1][2],acc[1][3], a0,a1,a2,a3, bl[k][2],bl[k][3]);
        }
        __syncthreads();

        {
            int r0 = lane >> 2, r1 = r0 + 8;
            #pragma unroll
            for (int s = 0; s < 2; s++) {
                int cs = c0 + s * 8 + (lane & 3) * 2;
                *(float2*)&OSf[r0][cs] = make_float2(acc[s][0], acc[s][1]);
                *(float2*)&OSf[r1][cs] = make_float2(acc[s][2], acc[s][3]);
            }
        }
        __syncthreads();

        {
            long row = ti * 16 + r;
            float4 va = *(float4*)&OSf[r][q * 8];
            float4 vb = *(float4*)&OSf[r][q * 8 + 4];
            if (RES) {
                uint4 hv = __ldcs((const uint4*)(hres + row * 64 + q * 8));
                const __half2* hp = (const __half2*)&hv;
                float2 h0 = __half22float2(hp[0]);
                float2 h1 = __half22float2(hp[1]);
                float2 h2 = __half22float2(hp[2]);
                float2 h3 = __half22float2(hp[3]);
                va.x += h0.x; va.y += h0.y; va.z += h1.x; va.w += h1.y;
                vb.x += h2.x; vb.y += h2.y; vb.z += h3.x; vb.w += h3.y;
            }
            float s = va.x + va.y + va.z + va.w + vb.x + vb.y + vb.z + vb.w;
            float ss = va.x*va.x + va.y*va.y + va.z*va.z + va.w*va.w
                     + vb.x*vb.x + vb.y*vb.y + vb.z*vb.z + vb.w*vb.w;
            #pragma unroll
            for (int m = 1; m < 8; m <<= 1) {
                s  += __shfl_xor_sync(0xffffffffu, s,  m);
                ss += __shfl_xor_sync(0xffffffffu, ss, m);
            }
            float mu = s * (1.0f / 64.0f);
            float var = fmaxf(ss * (1.0f / 64.0f) - mu * mu, 0.0f);
            float rs = rsqrtf(var + 1e-5f);
            float z0 = fmaxf(fmaf((va.x - mu) * rs, ga0.x, be0.x), 0.f);
            float z1 = fmaxf(fmaf((va.y - mu) * rs, ga0.y, be0.y), 0.f);
            float z2 = fmaxf(fmaf((va.z - mu) * rs, ga0.z, be0.z), 0.f);
            float z3 = fmaxf(fmaf((va.w - mu) * rs, ga0.w, be0.w), 0.f);
            float z4 = fmaxf(fmaf((vb.x - mu) * rs, ga1.x, be1.x), 0.f);
            float z5 = fmaxf(fmaf((vb.y - mu) * rs, ga1.y, be1.y), 0.f);
            float z6 = fmaxf(fmaf((vb.z - mu) * rs, ga1.z, be1.z), 0.f);
            float z7 = fmaxf(fmaf((vb.w - mu) * rs, ga1.w, be1.w), 0.f);
            if (!FINAL) {
                uint4 hv;
                hv.x = hf2u(va.x, va.y); hv.y = hf2u(va.z, va.w);
                hv.z = hf2u(vb.x, vb.y); hv.w = hf2u(vb.z, vb.w);
                *(uint4*)(houtH + row * 64 + q * 8) = hv;
            }
            uint4 zv;
            zv.x = hf2u(z0, z1); zv.y = hf2u(z2, z3);
            zv.z = hf2u(z4, z5); zv.w = hf2u(z6, z7);
            *(uint4*)(zoutH + row * 64 + q * 8) = zv;
        }
    }
}

// ---------------- aggregation: u = softmax-aggr + z (R8-proven form) ---------
#define AGG_GRID 1563
__global__ __launch_bounds__(256) void k_agg_lite(
    const __half2* __restrict__ z2, const float* __restrict__ tptr,
    __half2* __restrict__ uout)
{
    int t = threadIdx.x;
    int w = t >> 5, l = t & 31;
    float tv = __ldg(tptr);
    float kf = tv * 1.44269504f;
    const __half2 zero2 = __float2half2_rn(0.f);
    const __half2 eps2  = __float2half2_rn(1e-7f);
    const __half2* e2 = (const __half2*)g_eh;

    #pragma unroll 1
    for (int round = 0; round < 8; round++) {
        int node = round * (AGG_GRID * 8) + blockIdx.x * 8 + w;
        if (node >= NN) continue;

        int beg = g_offs[node], end = g_offs[node + 1];
        float d0 = 0.f, d1 = 0.f, s0 = 0.f, s1 = 0.f;
        int p = beg;
        for (; p + 4 <= end; p += 4) {
            __half2 ea = __ldcs(&e2[(size_t)p * 32 + l]);
            __half2 eb = __ldcs(&e2[(size_t)(p + 1) * 32 + l]);
            __half2 ec = __ldcs(&e2[(size_t)(p + 2) * 32 + l]);
            __half2 ed = __ldcs(&e2[(size_t)(p + 3) * 32 + l]);
            int i0 = __ldg(&g_srcn[p]);
            int i1 = __ldg(&g_srcn[p + 1]);
            int i2 = __ldg(&g_srcn[p + 2]);
            int i3 = __ldg(&g_srcn[p + 3]);
            __half2 za = __ldg(&z2[(size_t)i0 * 32 + l]);
            __half2 zb = __ldg(&z2[(size_t)i1 * 32 + l]);
            __half2 zc = __ldg(&z2[(size_t)i2 * 32 + l]);
            __half2 zd = __ldg(&z2[(size_t)i3 * 32 + l]);
            __half2 ma = __hadd2(__hmax2(__hadd2(ea, za), zero2), eps2);
            __half2 mb = __hadd2(__hmax2(__hadd2(eb, zb), zero2), eps2);
            __half2 mc = __hadd2(__hmax2(__hadd2(ec, zc), zero2), eps2);
            __half2 md = __hadd2(__hmax2(__hadd2(ed, zd), zero2), eps2);
            float m0, m1, x0, x1;
            m0 = __low2float(ma); m1 = __high2float(ma);
            x0 = ex2f(m0 * kf); x1 = ex2f(m1 * kf);
            d0 += x0; s0 = fmaf(x0, m0, s0);
            d1 += x1; s1 = fmaf(x1, m1, s1);
            m0 = __low2float(mb); m1 = __high2float(mb);
            x0 = ex2f(m0 * kf); x1 = ex2f(m1 * kf);
            d0 += x0; s0 = fmaf(x0, m0, s0);
            d1 += x1; s1 = fmaf(x1, m1, s1);
            m0 = __low2float(mc); m1 = __high2float(mc);
            x0 = ex2f(m0 * kf); x1 = ex2f(m1 * kf);
            d0 += x0; s0 = fmaf(x0, m0, s0);
            d1 += x1; s1 = fmaf(x1, m1, s1);
            m0 = __low2float(md); m1 = __high2float(md);
            x0 = ex2f(m0 * kf); x1 = ex2f(m1 * kf);
            d0 += x0; s0 = fmaf(x0, m0, s0);
            d1 += x1; s1 = fmaf(x1, m1, s1);
        }
        for (; p < end; p++) {
            __half2 ef = __ldcs(&e2[(size_t)p * 32 + l]);
            int si = __ldg(&g_srcn[p]);
            __half2 zv = __ldg(&z2[(size_t)si * 32 + l]);
            __half2 ma = __hadd2(__hmax2(__hadd2(ef, zv), zero2), eps2);
            float m0 = __low2float(ma), m1 = __high2float(ma);
            float x0 = ex2f(m0 * kf), x1 = ex2f(m1 * kf);
            d0 += x0; s0 = fmaf(x0, m0, s0);
            d1 += x1; s1 = fmaf(x1, m1, s1);
        }

        float2 zn = __half22float2(z2[(size_t)node * 32 + l]);
        float u0 = __fdividef(s0, d0 + 1e-16f) + zn.x;
        float u1 = __fdividef(s1, d1 + 1e-16f) + zn.y;
        uout[(size_t)node * 32 + l] = __floats2half2_rn(u0, u1);
    }
}

// ---------------- launch ----------------
extern "C" void kernel_launch(void* const* d_in, const int* in_sizes, int n_in,
                              void* d_out, int out_size)
{
    const float* x         = (const float*)d_in[0];
    const float* edge_attr = (const float*)d_in[1];
    const int*   ei        = (const int*)d_in[2];
    const float* W_ne      = (const float*)d_in[3];
    const float* b_ne      = (const float*)d_in[4];
    const float* W_ee      = (const float*)d_in[5];
    const float* b_ee      = (const float*)d_in[6];
    const float* W_conv    = (const float*)d_in[7];
    const float* b_conv    = (const float*)d_in[8];
    const float* tarr      = (const float*)d_in[9];
    const float* gamma     = (const float*)d_in[10];
    const float* beta      = (const float*)d_in[11];
    const float* W_lin     = (const float*)d_in[12];
    const float* b_lin     = (const float*)d_in[13];
    float* out = (float*)d_out;

    __half *p_eh, *p_zh0, *p_zh1, *p_u, *p_hA, *p_hB;
    int *p_pos;
    cudaGetSymbolAddress((void**)&p_eh,  g_eh);
    cudaGetSymbolAddress((void**)&p_zh0, g_zh0);
    cudaGetSymbolAddress((void**)&p_zh1, g_zh1);
    cudaGetSymbolAddress((void**)&p_u,   g_u);
    cudaGetSymbolAddress((void**)&p_hA,  g_hA);
    cudaGetSymbolAddress((void**)&p_hB,  g_hB);
    cudaGetSymbolAddress((void**)&p_pos, g_pos);

    const int NB_E  = (NE + 255) / 256;
    const int NB_S  = (NN + 1023) / 1024;
    const int NB_SC = (NN + 255) / 256;

    // node encoder (blocks 0..624) + edge histogram (blocks 625..13124), concurrent
    k_node_hist<10><<<625 + (NE + 127) / 128, 128>>>(x, W_ne, b_ne, p_zh0, ei);
    // CSR prefix + scatter
    k_scan1 <<<NB_S, 1024>>>();
    k_scan23<<<NB_SC, 256>>>();
    k_scatter<<<NB_E, 256>>>(ei);
    // edge encoder (scatters to CSR order)
    k_gemm_edge<16><<<6250, 128>>>(edge_attr, W_ee, b_ee, p_eh, p_pos);

    // layer 0
    k_agg_lite<<<AGG_GRID, 256>>>((const __half2*)p_zh0, tarr, (__half2*)p_u);
    k_gemm_conv<false, false, 10><<<625, 128>>>(p_u, W_conv, b_conv, nullptr,
        gamma + 64, beta + 64, p_hB, p_zh1);
    // layer 1
    k_agg_lite<<<AGG_GRID, 256>>>((const __half2*)p_zh1, tarr + 1, (__half2*)p_u);
    k_gemm_conv<true, false, 10><<<625, 128>>>(p_u, W_conv + 4096, b_conv + 64, p_hB,
        gamma + 128, beta + 128, p_hA, p_zh0);
    // layer 2
    k_agg_lite<<<AGG_GRID, 256>>>((const __half2*)p_zh0, tarr + 2, (__half2*)p_u);
    k_gemm_conv<true, false, 10><<<625, 128>>>(p_u, W_conv + 8192, b_conv + 128, p_hA,
        gamma + 192, beta + 192, p_hB, p_zh1);
    // layer 3 (FINAL: z fp16 only, LN with gamma0/beta0)
    k_agg_lite<<<AGG_GRID, 256>>>((const __half2*)p_zh1, tarr + 3, (__half2*)p_u);
    k_gemm_conv<true, true, 10><<<625, 128>>>(p_u, W_conv + 12288, b_conv + 192, p_hB,
        gamma, beta, nullptr, p_zh0);

    // final linear (fp16 z input)
    k_gemm_h16<10><<<625, 128>>>(p_zh0, W_lin, b_lin, out);
}

// round 16
// speedup vs baseline: 1.1028x; 1.0578x over previous
#include <cuda_runtime.h>
#include <cuda_fp16.h>
#include <cuda_bf16.h>
#include <cstdint>

#define NN 100000
#define NE 1600000

// ---------------- device scratch ----------------
__device__ __half g_eh[(size_t)NE * 64];    // edge features fp16, CSR order
__device__ __half g_zh0[(size_t)NN * 64];
__device__ __half g_zh1[(size_t)NN * 64];
__device__ __half g_u[(size_t)NN * 64];
__device__ __half g_hA[(size_t)NN * 64];    // residual h, fp16
__device__ __half g_hB[(size_t)NN * 64];
__device__ int    g_srcn[NE];
__device__ int    g_pos[NE];
__device__ int    g_rank[NE];
__device__ int    g_offs[NN + 1];
__device__ int    g_deg[NN];
__device__ int    g_bsum[128];

// ---------------- CSR build ----------------
__global__ void k_scan1() {
    int t = threadIdx.x;
    int idx = blockIdx.x * 1024 + t;
    int v = (idx < NN) ? g_deg[idx] : 0;
    if (idx < NN) g_deg[idx] = 0;
    int x = v;
    int lane = t & 31, w = t >> 5;
    #pragma unroll
    for (int o = 1; o < 32; o <<= 1) {
        int y = __shfl_up_sync(0xffffffffu, x, o);
        if (lane >= o) x += y;
    }
    __shared__ int ws[32];
    if (lane == 31) ws[w] = x;
    __syncthreads();
    if (w == 0) {
        int y = ws[lane];
        #pragma unroll
        for (int o = 1; o < 32; o <<= 1) {
            int z2 = __shfl_up_sync(0xffffffffu, y, o);
            if (lane >= o) y += z2;
        }
        ws[lane] = y;
    }
    __syncthreads();
    int incl = x + (w > 0 ? ws[w - 1] : 0);
    if (idx < NN) g_offs[idx] = incl - v;
    if (t == 1023) g_bsum[blockIdx.x] = incl;
}
__global__ __launch_bounds__(256) void k_scan23() {
    __shared__ int bs[128];
    __shared__ int ws[4];
    int t = threadIdx.x;
    const int nb = (NN + 1023) >> 10;
    int v = 0, x = 0;
    int lane = t & 31, w = t >> 5;
    if (t < 128) {
        v = (t < nb) ? g_bsum[t] : 0;
        x = v;
        #pragma unroll
        for (int o = 1; o < 32; o <<= 1) {
            int y = __shfl_up_sync(0xffffffffu, x, o);
            if (lane >= o) x += y;
        }
        if (lane == 31) ws[w] = x;
    }
    __syncthreads();
    if (t < 128) {
        int add = 0;
        if (w == 1) add = ws[0];
        else if (w == 2) add = ws[0] + ws[1];
        else if (w == 3) add = ws[0] + ws[1] + ws[2];
        bs[t] = x + add - v;
    }
    __syncthreads();
    int idx = blockIdx.x * 256 + t;
    if (idx < NN) g_offs[idx] += bs[idx >> 10];
    if (idx == 0) g_offs[NN] = NE;
}
// scatter now writes only coalesced pos (srcn moves to the edge GEMM epilogue)
__global__ void k_scatter(const int* __restrict__ ei) {
    int i = blockIdx.x * blockDim.x + threadIdx.x;
    if (i < NE)
        g_pos[i] = g_offs[ei[NE + i]] + g_rank[i];
}

// ---------------- GEMM plumbing ----------------
#define LDSM4(R0,R1,R2,R3,ADDR) \
    asm volatile("ldmatrix.sync.aligned.m8n8.x4.shared.b16 {%0,%1,%2,%3}, [%4];" \
        : "=r"(R0),"=r"(R1),"=r"(R2),"=r"(R3) : "r"(ADDR))
#define MMA_F16(C0,C1,C2,C3,A0,A1,A2,A3,B0,B1) \
    asm volatile("mma.sync.aligned.m16n8k16.row.col.f32.f16.f16.f32 " \
        "{%0,%1,%2,%3},{%4,%5,%6,%7},{%8,%9},{%0,%1,%2,%3};" \
        : "+f"(C0),"+f"(C1),"+f"(C2),"+f"(C3) \
        : "r"(A0),"r"(A1),"r"(A2),"r"(A3),"r"(B0),"r"(B1))

__device__ __forceinline__ uint32_t sm_addr(const void* p) {
    return (uint32_t)__cvta_generic_to_shared(p);
}
__device__ __forceinline__ uint32_t hf2u(float a, float b) {
    __half2 v = __floats2half2_rn(a, b);
    return *(uint32_t*)&v;
}
__device__ __forceinline__ float ex2f(float x) {
    float r; asm("ex2.approx.f32 %0, %1;" : "=f"(r) : "f"(x)); return r;
}

// ---------------- node encoder (blocks 0..624) + edge histogram (rest) -------
template<int TILES>
__global__ __launch_bounds__(128) void k_node_hist(
    const float* __restrict__ A,
    const float* __restrict__ W, const float* __restrict__ bias,
    __half* __restrict__ outH, const int* __restrict__ ei)
{
    __shared__ __align__(16) char smraw[9216];

    if (blockIdx.x >= 625) {
        int i = (blockIdx.x - 625) * 128 + threadIdx.x;
        if (i < NE) g_rank[i] = atomicAdd(&g_deg[ei[NE + i]], 1);
        return;
    }

    __half (*Wh)[72]  = (__half(*)[72])smraw;
    __half (*Ahh)[72] = (__half(*)[72])smraw;

    int t = threadIdx.x;
    int w = t >> 5, lane = t & 31;
    int tr = lane & 7, sel = lane >> 3;

    for (int i = t; i < 4096; i += 128) {
        int k = i >> 6, n = i & 63;
        Wh[n][k] = __float2half_rn(W[i]);
    }
    __syncthreads();

    int c0 = w * 16;
    uint32_t bh[4][4];
    {
        int bn = c0 + tr + ((sel & 2) << 2);
        #pragma unroll
        for (int k = 0; k < 4; k++) {
            int bk = 16 * k + ((sel & 1) << 3);
            LDSM4(bh[k][0], bh[k][1], bh[k][2], bh[k][3], sm_addr(&Wh[bn][bk]));
        }
    }
    __syncthreads();

    float bi[2][2];
    #pragma unroll
    for (int s = 0; s < 2; s++) {
        int cs = c0 + s * 8 + (lane & 3) * 2;
        bi[s][0] = __ldg(&bias[cs]);
        bi[s][1] = __ldg(&bias[cs + 1]);
    }

    int r = t >> 3, q = t & 7;
    int ar = tr + ((sel & 1) << 3);

    long ti0 = (long)blockIdx.x * TILES;
    float4 pfa = __ldcs((const float4*)(A + (ti0 * 16 + r) * 64 + q * 8));
    float4 pfb = __ldcs((const float4*)(A + (ti0 * 16 + r) * 64 + q * 8 + 4));

    for (int it = 0; it < TILES; it++) {
        long ti = ti0 + it;
        {
            uint4 hv;
            hv.x = hf2u(pfa.x, pfa.y); hv.y = hf2u(pfa.z, pfa.w);
            hv.z = hf2u(pfb.x, pfb.y); hv.w = hf2u(pfb.z, pfb.w);
            *(uint4*)&Ahh[r][q * 8] = hv;
        }
        __syncthreads();

        if (it + 1 < TILES) {
            pfa = __ldcs((const float4*)(A + ((ti + 1) * 16 + r) * 64 + q * 8));
            pfb = __ldcs((const float4*)(A + ((ti + 1) * 16 + r) * 64 + q * 8 + 4));
        }

        float acc[2][4];
        #pragma unroll
        for (int s = 0; s < 2; s++) {
            acc[s][0] = bi[s][0]; acc[s][1] = bi[s][1];
            acc[s][2] = bi[s][0]; acc[s][3] = bi[s][1];
        }

        #pragma unroll
        for (int k = 0; k < 4; k++) {
            int ak = 16 * k + ((sel >> 1) << 3);
            uint32_t a0, a1, a2, a3;
            LDSM4(a0, a1, a2, a3, sm_addr(&Ahh[ar][ak]));
            MMA_F16(acc[0][0],acc[0][1],acc[0][2],acc[0][3], a0,a1,a2,a3, bh[k][0],bh[k][1]);
            MMA_F16(acc[1][0],acc[1][1],acc[1][2],acc[1][3], a0,a1,a2,a3, bh[k][2],bh[k][3]);
        }
        __syncthreads();

        long rg0 = ti * 16 + (lane >> 2);
        long rg1 = rg0 + 8;
        #pragma unroll
        for (int s = 0; s < 2; s++) {
            int cs = c0 + s * 8 + (lane & 3) * 2;
            *(__half2*)(outH + rg0 * 64 + cs) = __floats2half2_rn(acc[s][0], acc[s][1]);
            *(__half2*)(outH + rg1 * 64 + cs) = __floats2half2_rn(acc[s][2], acc[s][3]);
        }
    }
}

// ---------------- edge encoder: fp16 single-pass, direct scatter + srcn write -
template<int TILES>
__global__ __launch_bounds__(128) void k_gemm_edge(
    const float* __restrict__ A, const int* __restrict__ ei,
    const float* __restrict__ W, const float* __restrict__ bias,
    __half* __restrict__ outH, const int* __restrict__ pos)
{
    __shared__ __align__(16) char smraw[9216];
    __half (*Wh)[72]  = (__half(*)[72])smraw;
    __half (*Ahh)[72] = (__half(*)[72])smraw;

    int t = threadIdx.x;
    int w = t >> 5, lane = t & 31;
    int tr = lane & 7, sel = lane >> 3;

    for (int i = t; i < 4096; i += 128) {
        int k = i >> 6, n = i & 63;
        Wh[n][k] = __float2half_rn(W[i]);
    }
    __syncthreads();

    int c0 = w * 16;
    uint32_t bh[4][4];
    {
        int bn = c0 + tr + ((sel & 2) << 2);
        #pragma unroll
        for (int k = 0; k < 4; k++) {
            int bk = 16 * k + ((sel & 1) << 3);
            LDSM4(bh[k][0], bh[k][1], bh[k][2], bh[k][3], sm_addr(&Wh[bn][bk]));
        }
    }
    __syncthreads();

    float bi[2][2];
    #pragma unroll
    for (int s = 0; s < 2; s++) {
        int cs = c0 + s * 8 + (lane & 3) * 2;
        bi[s][0] = __ldg(&bias[cs]);
        bi[s][1] = __ldg(&bias[cs + 1]);
    }

    int r = t >> 3, q = t & 7;
    int ar = tr + ((sel & 1) << 3);

    long ti0 = (long)blockIdx.x * TILES;
    float4 pfa = __ldcs((const float4*)(A + (ti0 * 16 + r) * 64 + q * 8));
    float4 pfb = __ldcs((const float4*)(A + (ti0 * 16 + r) * 64 + q * 8 + 4));

    for (int it = 0; it < TILES; it++) {
        long ti = ti0 + it;
        {
            uint4 hv;
            hv.x = hf2u(pfa.x, pfa.y); hv.y = hf2u(pfa.z, pfa.w);
            hv.z = hf2u(pfb.x, pfb.y); hv.w = hf2u(pfb.z, pfb.w);
            *(uint4*)&Ahh[r][q * 8] = hv;
        }
        __syncthreads();

        if (it + 1 < TILES) {
            pfa = __ldcs((const float4*)(A + ((ti + 1) * 16 + r) * 64 + q * 8));
            pfb = __ldcs((const float4*)(A + ((ti + 1) * 16 + r) * 64 + q * 8 + 4));
        }

        float acc[2][4];
        #pragma unroll
        for (int s = 0; s < 2; s++) {
            acc[s][0] = bi[s][0]; acc[s][1] = bi[s][1];
            acc[s][2] = bi[s][0]; acc[s][3] = bi[s][1];
        }

        #pragma unroll
        for (int k = 0; k < 4; k++) {
            int ak = 16 * k + ((sel >> 1) << 3);
            uint32_t a0, a1, a2, a3;
            LDSM4(a0, a1, a2, a3, sm_addr(&Ahh[ar][ak]));
            MMA_F16(acc[0][0],acc[0][1],acc[0][2],acc[0][3], a0,a1,a2,a3, bh[k][0],bh[k][1]);
            MMA_F16(acc[1][0],acc[1][1],acc[1][2],acc[1][3], a0,a1,a2,a3, bh[k][2],bh[k][3]);
        }
        __syncthreads();

        long row0 = ti * 16 + (lane >> 2);
        long p0 = (long)__ldg(&pos[row0]);
        long p1 = (long)__ldg(&pos[row0 + 8]);
        #pragma unroll
        for (int s = 0; s < 2; s++) {
            int cs = c0 + s * 8 + (lane & 3) * 2;
            *(__half2*)(outH + p0 * 64 + cs) = __floats2half2_rn(acc[s][0], acc[s][1]);
            *(__half2*)(outH + p1 * 64 + cs) = __floats2half2_rn(acc[s][2], acc[s][3]);
        }
        // warp 0 lane-leaders also publish srcn for these rows
        if (w == 0 && (lane & 3) == 0) {
            g_srcn[p0] = __ldg(&ei[row0]);
            g_srcn[p1] = __ldg(&ei[row0 + 8]);
        }
    }
}

// ---------------- final linear: fp16 A single-pass, W fp16 hi/lo, fp32 out ----
template<int TILES>
__global__ __launch_bounds__(128) void k_gemm_h16(
    const __half* __restrict__ A,
    const float* __restrict__ W, const float* __restrict__ bias,
    float* __restrict__ outF)
{
    __shared__ __align__(16) char smraw[18432];
    __half (*Wh)[72]  = (__half(*)[72])smraw;
    __half (*Wl)[72]  = (__half(*)[72])(smraw + 9216);
    __half (*Ahh)[72] = (__half(*)[72])smraw;

    int t = threadIdx.x;
    int w = t >> 5, lane = t & 31;
    int tr = lane & 7, sel = lane >> 3;

    for (int i = t; i < 4096; i += 128) {
        int k = i >> 6, n = i & 63;
        float wv = W[i];
        __half h = __float2half_rn(wv);
        Wh[n][k] = h;
        Wl[n][k] = __float2half_rn(wv - __half2float(h));
    }
    __syncthreads();

    int c0 = w * 16;
    uint32_t bh[4][4], bl[4][4];
    {
        int bn = c0 + tr + ((sel & 2) << 2);
        #pragma unroll
        for (int k = 0; k < 4; k++) {
            int bk = 16 * k + ((sel & 1) << 3);
            LDSM4(bh[k][0], bh[k][1], bh[k][2], bh[k][3], sm_addr(&Wh[bn][bk]));
            LDSM4(bl[k][0], bl[k][1], bl[k][2], bl[k][3], sm_addr(&Wl[bn][bk]));
        }
    }
    __syncthreads();

    float bi[2][2];
    #pragma unroll
    for (int s = 0; s < 2; s++) {
        int cs = c0 + s * 8 + (lane & 3) * 2;
        bi[s][0] = __ldg(&bias[cs]);
        bi[s][1] = __ldg(&bias[cs + 1]);
    }

    int r = t >> 3, q = t & 7;
    int ar = tr + ((sel & 1) << 3);

    long ti0 = (long)blockIdx.x * TILES;
    uint4 pfu = __ldcs((const uint4*)(A + (ti0 * 16 + r) * 64 + q * 8));

    for (int it = 0; it < TILES; it++) {
        long ti = ti0 + it;
        *(uint4*)&Ahh[r][q * 8] = pfu;
        __syncthreads();

        if (it + 1 < TILES)
            pfu = __ldcs((const uint4*)(A + ((ti + 1) * 16 + r) * 64 + q * 8));

        float acc[2][4];
        #pragma unroll
        for (int s = 0; s < 2; s++) {
            acc[s][0] = bi[s][0]; acc[s][1] = bi[s][1];
            acc[s][2] = bi[s][0]; acc[s][3] = bi[s][1];
        }

        #pragma unroll
        for (int k = 0; k < 4; k++) {
            int ak = 16 * k + ((sel >> 1) << 3);
            uint32_t a0, a1, a2, a3;
            LDSM4(a0, a1, a2, a3, sm_addr(&Ahh[ar][ak]));
            MMA_F16(acc[0][0],acc[0][1],acc[0][2],acc[0][3], a0,a1,a2,a3, bh[k][0],bh[k][1]);
            MMA_F16(acc[0][0],acc[0][1],acc[0][2],acc[0][3], a0,a1,a2,a3, bl[k][0],bl[k][1]);
            MMA_F16(acc[1][0],acc[1][1],acc[1][2],acc[1][3], a0,a1,a2,a3, bh[k][2],bh[k][3]);
            MMA_F16(acc[1][0],acc[1][1],acc[1][2],acc[1][3], a0,a1,a2,a3, bl[k][2],bl[k][3]);
        }
        __syncthreads();

        long rg0 = ti * 16 + (lane >> 2);
        long rg1 = rg0 + 8;
        #pragma unroll
        for (int s = 0; s < 2; s++) {
            int cs = c0 + s * 8 + (lane & 3) * 2;
            *(float2*)(outF + rg0 * 64 + cs) = make_float2(acc[s][0], acc[s][1]);
            *(float2*)(outF + rg1 * 64 + cs) = make_float2(acc[s][2], acc[s][3]);
        }
    }
}

// ---------------- conv GEMM (u fp16 exact, W fp16 hi/lo) + LN epilogue --------
template<bool RES, bool FINAL, int TILES>
__global__ __launch_bounds__(128) void k_gemm_conv(
    const __half* __restrict__ U,
    const float* __restrict__ W, const float* __restrict__ bias,
    const __half* __restrict__ hres,
    const float* __restrict__ gamma, const float* __restrict__ beta,
    __half* __restrict__ houtH, __half* __restrict__ zoutH)
{
    __shared__ __align__(16) char smraw[18432];
    __half (*Wh)[72]  = (__half(*)[72])smraw;
    __half (*Wl)[72]  = (__half(*)[72])(smraw + 9216);
    __half (*Ahh)[72] = (__half(*)[72])smraw;
    float  (*OSf)[72] = (float(*)[72]) (smraw + 2304);

    int t = threadIdx.x;
    int w = t >> 5, lane = t & 31;
    int tr = lane & 7, sel = lane >> 3;

    for (int i = t; i < 4096; i += 128) {
        int k = i >> 6, n = i & 63;
        float wv = W[i];
        __half h = __float2half_rn(wv);
        Wh[n][k] = h;
        Wl[n][k] = __float2half_rn(wv - __half2float(h));
    }
    __syncthreads();

    int c0 = w * 16;
    uint32_t bh[4][4], bl[4][4];
    {
        int bn = c0 + tr + ((sel & 2) << 2);
        #pragma unroll
        for (int k = 0; k < 4; k++) {
            int bk = 16 * k + ((sel & 1) << 3);
            LDSM4(bh[k][0], bh[k][1], bh[k][2], bh[k][3], sm_addr(&Wh[bn][bk]));
            LDSM4(bl[k][0], bl[k][1], bl[k][2], bl[k][3], sm_addr(&Wl[bn][bk]));
        }
    }
    __syncthreads();

    float bi[2][2];
    #pragma unroll
    for (int s = 0; s < 2; s++) {
        int cs = c0 + s * 8 + (lane & 3) * 2;
        bi[s][0] = __ldg(&bias[cs]);
        bi[s][1] = __ldg(&bias[cs + 1]);
    }

    int r = t >> 3, q = t & 7;
    int ar = tr + ((sel & 1) << 3);

    float4 ga0 = __ldg((const float4*)(gamma + q * 8));
    float4 ga1 = __ldg((const float4*)(gamma + q * 8 + 4));
    float4 be0 = __ldg((const float4*)(beta  + q * 8));
    float4 be1 = __ldg((const float4*)(beta  + q * 8 + 4));

    long ti0 = (long)blockIdx.x * TILES;
    uint4 pfu = __ldcs((const uint4*)(U + (ti0 * 16 + r) * 64 + q * 8));

    for (int it = 0; it < TILES; it++) {
        long ti = ti0 + it;
        *(uint4*)&Ahh[r][q * 8] = pfu;
        __syncthreads();

        if (it + 1 < TILES)
            pfu = __ldcs((const uint4*)(U + ((ti + 1) * 16 + r) * 64 + q * 8));

        float acc[2][4];
        #pragma unroll
        for (int s = 0; s < 2; s++) {
            acc[s][0] = bi[s][0]; acc[s][1] = bi[s][1];
            acc[s][2] = bi[s][0]; acc[s][3] = bi[s][1];
        }

        #pragma unroll
        for (int k = 0; k < 4; k++) {
            int ak = 16 * k + ((sel >> 1) << 3);
            uint32_t a0, a1, a2, a3;
            LDSM4(a0, a1, a2, a3, sm_addr(&Ahh[ar][ak]));
            MMA_F16(acc[0][0],acc[0][1],acc[0][2],acc[0][3], a0,a1,a2,a3, bh[k][0],bh[k][1]);
            MMA_F16(acc[0][0],acc[0][1],acc[0][2],acc[0][3], a0,a1,a2,a3, bl[k][0],bl[k][1]);
            MMA_F16(acc[1][0],acc[1][1],acc[1][2],acc[1][3], a0,a1,a2,a3, bh[k][2],bh[k][3]);
            MMA_F16(acc[1][0],acc[1][1],acc[1][2],acc[1][3], a0,a1,a2,a3, bl[k][2],bl[k][3]);
        }
        __syncthreads();

        {
            int r0 = lane >> 2, r1 = r0 + 8;
            #pragma unroll
            for (int s = 0; s < 2; s++) {
                int cs = c0 + s * 8 + (lane & 3) * 2;
                *(float2*)&OSf[r0][cs] = make_float2(acc[s][0], acc[s][1]);
                *(float2*)&OSf[r1][cs] = make_float2(acc[s][2], acc[s][3]);
            }
        }
        __syncthreads();

        {
            long row = ti * 16 + r;
            float4 va = *(float4*)&OSf[r][q * 8];
            float4 vb = *(float4*)&OSf[r][q * 8 + 4];
            if (RES) {
                uint4 hv = __ldcs((const uint4*)(hres + row * 64 + q * 8));
                const __half2* hp = (const __half2*)&hv;
                float2 h0 = __half22float2(hp[0]);
                float2 h1 = __half22float2(hp[1]);
                float2 h2 = __half22float2(hp[2]);
                float2 h3 = __half22float2(hp[3]);
                va.x += h0.x; va.y += h0.y; va.z += h1.x; va.w += h1.y;
                vb.x += h2.x; vb.y += h2.y; vb.z += h3.x; vb.w += h3.y;
            }
            float s = va.x + va.y + va.z + va.w + vb.x + vb.y + vb.z + vb.w;
            float ss = va.x*va.x + va.y*va.y + va.z*va.z + va.w*va.w
                     + vb.x*vb.x + vb.y*vb.y + vb.z*vb.z + vb.w*vb.w;
            #pragma unroll
            for (int m = 1; m < 8; m <<= 1) {
                s  += __shfl_xor_sync(0xffffffffu, s,  m);
                ss += __shfl_xor_sync(0xffffffffu, ss, m);
            }
            float mu = s * (1.0f / 64.0f);
            float var = fmaxf(ss * (1.0f / 64.0f) - mu * mu, 0.0f);
            float rs = rsqrtf(var + 1e-5f);
            float z0 = fmaxf(fmaf((va.x - mu) * rs, ga0.x, be0.x), 0.f);
            float z1 = fmaxf(fmaf((va.y - mu) * rs, ga0.y, be0.y), 0.f);
            float z2 = fmaxf(fmaf((va.z - mu) * rs, ga0.z, be0.z), 0.f);
            float z3 = fmaxf(fmaf((va.w - mu) * rs, ga0.w, be0.w), 0.f);
            float z4 = fmaxf(fmaf((vb.x - mu) * rs, ga1.x, be1.x), 0.f);
            float z5 = fmaxf(fmaf((vb.y - mu) * rs, ga1.y, be1.y), 0.f);
            float z6 = fmaxf(fmaf((vb.z - mu) * rs, ga1.z, be1.z), 0.f);
            float z7 = fmaxf(fmaf((vb.w - mu) * rs, ga1.w, be1.w), 0.f);
            if (!FINAL) {
                uint4 hv;
                hv.x = hf2u(va.x, va.y); hv.y = hf2u(va.z, va.w);
                hv.z = hf2u(vb.x, vb.y); hv.w = hf2u(vb.z, vb.w);
                *(uint4*)(houtH + row * 64 + q * 8) = hv;
            }
            uint4 zv;
            zv.x = hf2u(z0, z1); zv.y = hf2u(z2, z3);
            zv.z = hf2u(z4, z5); zv.w = hf2u(z6, z7);
            *(uint4*)(zoutH + row * 64 + q * 8) = zv;
        }
    }
}

// ---------------- aggregation: finer granularity, 4 nodes/warp ---------------
#define AGG_GRID 3125
#define AGG_ROUNDS 4
__global__ __launch_bounds__(256) void k_agg_lite(
    const __half2* __restrict__ z2, const float* __restrict__ tptr,
    __half2* __restrict__ uout)
{
    int t = threadIdx.x;
    int w = t >> 5, l = t & 31;
    float tv = __ldg(tptr);
    float kf = tv * 1.44269504f;
    const __half2 zero2 = __float2half2_rn(0.f);
    const __half2 eps2  = __float2half2_rn(1e-7f);
    const __half2* e2 = (const __half2*)g_eh;

    #pragma unroll 1
    for (int round = 0; round < AGG_ROUNDS; round++) {
        int node = round * (AGG_GRID * 8) + blockIdx.x * 8 + w;
        if (node >= NN) continue;

        int beg = g_offs[node], end = g_offs[node + 1];
        float d0 = 0.f, d1 = 0.f, s0 = 0.f, s1 = 0.f;
        int p = beg;
        for (; p + 4 <= end; p += 4) {
            __half2 ea = __ldcs(&e2[(size_t)p * 32 + l]);
            __half2 eb = __ldcs(&e2[(size_t)(p + 1) * 32 + l]);
            __half2 ec = __ldcs(&e2[(size_t)(p + 2) * 32 + l]);
            __half2 ed = __ldcs(&e2[(size_t)(p + 3) * 32 + l]);
            int i0 = __ldg(&g_srcn[p]);
            int i1 = __ldg(&g_srcn[p + 1]);
            int i2 = __ldg(&g_srcn[p + 2]);
            int i3 = __ldg(&g_srcn[p + 3]);
            __half2 za = __ldg(&z2[(size_t)i0 * 32 + l]);
            __half2 zb = __ldg(&z2[(size_t)i1 * 32 + l]);
            __half2 zc = __ldg(&z2[(size_t)i2 * 32 + l]);
            __half2 zd = __ldg(&z2[(size_t)i3 * 32 + l]);
            __half2 ma = __hadd2(__hmax2(__hadd2(ea, za), zero2), eps2);
            __half2 mb = __hadd2(__hmax2(__hadd2(eb, zb), zero2), eps2);
            __half2 mc = __hadd2(__hmax2(__hadd2(ec, zc), zero2), eps2);
            __half2 md = __hadd2(__hmax2(__hadd2(ed, zd), zero2), eps2);
            float m0, m1, x0, x1;
            m0 = __low2float(ma); m1 = __high2float(ma);
            x0 = ex2f(m0 * kf); x1 = ex2f(m1 * kf);
            d0 += x0; s0 = fmaf(x0, m0, s0);
            d1 += x1; s1 = fmaf(x1, m1, s1);
            m0 = __low2float(mb); m1 = __high2float(mb);
            x0 = ex2f(m0 * kf); x1 = ex2f(m1 * kf);
            d0 += x0; s0 = fmaf(x0, m0, s0);
            d1 += x1; s1 = fmaf(x1, m1, s1);
            m0 = __low2float(mc); m1 = __high2float(mc);
            x0 = ex2f(m0 * kf); x1 = ex2f(m1 * kf);
            d0 += x0; s0 = fmaf(x0, m0, s0);
            d1 += x1; s1 = fmaf(x1, m1, s1);
            m0 = __low2float(md); m1 = __high2float(md);
            x0 = ex2f(m0 * kf); x1 = ex2f(m1 * kf);
            d0 += x0; s0 = fmaf(x0, m0, s0);
            d1 += x1; s1 = fmaf(x1, m1, s1);
        }
        for (; p < end; p++) {
            __half2 ef = __ldcs(&e2[(size_t)p * 32 + l]);
            int si = __ldg(&g_srcn[p]);
            __half2 zv = __ldg(&z2[(size_t)si * 32 + l]);
            __half2 ma = __hadd2(__hmax2(__hadd2(ef, zv), zero2), eps2);
            float m0 = __low2float(ma), m1 = __high2float(ma);
            float x0 = ex2f(m0 * kf), x1 = ex2f(m1 * kf);
            d0 += x0; s0 = fmaf(x0, m0, s0);
            d1 += x1; s1 = fmaf(x1, m1, s1);
        }

        float2 zn = __half22float2(z2[(size_t)node * 32 + l]);
        float u0 = __fdividef(s0, d0 + 1e-16f) + zn.x;
        float u1 = __fdividef(s1, d1 + 1e-16f) + zn.y;
        uout[(size_t)node * 32 + l] = __floats2half2_rn(u0, u1);
    }
}

// ---------------- launch ----------------
extern "C" void kernel_launch(void* const* d_in, const int* in_sizes, int n_in,
                              void* d_out, int out_size)
{
    const float* x         = (const float*)d_in[0];
    const float* edge_attr = (const float*)d_in[1];
    const int*   ei        = (const int*)d_in[2];
    const float* W_ne      = (const float*)d_in[3];
    const float* b_ne      = (const float*)d_in[4];
    const float* W_ee      = (const float*)d_in[5];
    const float* b_ee      = (const float*)d_in[6];
    const float* W_conv    = (const float*)d_in[7];
    const float* b_conv    = (const float*)d_in[8];
    const float* tarr      = (const float*)d_in[9];
    const float* gamma     = (const float*)d_in[10];
    const float* beta      = (const float*)d_in[11];
    const float* W_lin     = (const float*)d_in[12];
    const float* b_lin     = (const float*)d_in[13];
    float* out = (float*)d_out;

    __half *p_eh, *p_zh0, *p_zh1, *p_u, *p_hA, *p_hB;
    int *p_pos;
    cudaGetSymbolAddress((void**)&p_eh,  g_eh);
    cudaGetSymbolAddress((void**)&p_zh0, g_zh0);
    cudaGetSymbolAddress((void**)&p_zh1, g_zh1);
    cudaGetSymbolAddress((void**)&p_u,   g_u);
    cudaGetSymbolAddress((void**)&p_hA,  g_hA);
    cudaGetSymbolAddress((void**)&p_hB,  g_hB);
    cudaGetSymbolAddress((void**)&p_pos, g_pos);

    const int NB_E  = (NE + 255) / 256;
    const int NB_S  = (NN + 1023) / 1024;
    const int NB_SC = (NN + 255) / 256;

    // node encoder + edge histogram (concurrent)
    k_node_hist<10><<<625 + (NE + 127) / 128, 128>>>(x, W_ne, b_ne, p_zh0, ei);
    // CSR prefix + pos
    k_scan1 <<<NB_S, 1024>>>();
    k_scan23<<<NB_SC, 256>>>();
    k_scatter<<<NB_E, 256>>>(ei);
    // edge encoder (scatters e rows + srcn to CSR order)
    k_gemm_edge<16><<<6250, 128>>>(edge_attr, ei, W_ee, b_ee, p_eh, p_pos);

    // layer 0
    k_agg_lite<<<AGG_GRID, 256>>>((const __half2*)p_zh0, tarr, (__half2*)p_u);
    k_gemm_conv<false, false, 10><<<625, 128>>>(p_u, W_conv, b_conv, nullptr,
        gamma + 64, beta + 64, p_hB, p_zh1);
    // layer 1
    k_agg_lite<<<AGG_GRID, 256>>>((const __half2*)p_zh1, tarr + 1, (__half2*)p_u);
    k_gemm_conv<true, false, 10><<<625, 128>>>(p_u, W_conv + 4096, b_conv + 64, p_hB,
        gamma + 128, beta + 128, p_hA, p_zh0);
    // layer 2
    k_agg_lite<<<AGG_GRID, 256>>>((const __half2*)p_zh0, tarr + 2, (__half2*)p_u);
    k_gemm_conv<true, false, 10><<<625, 128>>>(p_u, W_conv + 8192, b_conv + 128, p_hA,
        gamma + 192, beta + 192, p_hB, p_zh1);
    // layer 3 (FINAL: z fp16 only, LN with gamma0/beta0)
    k_agg_lite<<<AGG_GRID, 256>>>((const __half2*)p_zh1, tarr + 3, (__half2*)p_u);
    k_gemm_conv<true, true, 10><<<625, 128>>>(p_u, W_conv + 12288, b_conv + 192, p_hB,
        gamma, beta, nullptr, p_zh0);

    // final linear (fp16 z input)
    k_gemm_h16<10><<<625, 128>>>(p_zh0, W_lin, b_lin, out);
}